// round 1
// baseline (speedup 1.0000x reference)
#include <cuda_runtime.h>
#include <cuda_bf16.h>
#include <math.h>

#define Bc 8
#define Ec 1024
#define Dc 256
#define Hc 8
#define HDc 32
#define NBc 6
#define Mrows (Bc*Ec)   // 8192
#define FF (4*Dc)       // 1024

// ---------------- scratch (device globals; no allocation allowed) -------------
__device__ float g_q[Bc*Hc*Ec*HDc];     // [B,H,E,HD]
__device__ float g_k[Bc*Hc*Ec*HDc];
__device__ float g_v[Bc*Hc*Ec*HDc];
__device__ float g_attn[Mrows*Dc];      // [B,E,D]
__device__ float g_res1[Mrows*Dc];
__device__ float g_h1[Mrows*Dc];
__device__ float g_ff1[Mrows*FF];
__device__ float g_res2[Mrows*Dc];
__device__ int   g_mask[Bc*Ec];
__device__ int   g_flag[1];

// ---------------- mask dtype detection --------------------------------------
// If the bool mask arrives as int32, bytes at (i%4 != 0) over the first 8192
// bytes are all zero. If it arrives as uint8, they're random 0/1.
__global__ void detect_mask_kernel(const unsigned char* __restrict__ raw) {
    __shared__ int found;
    if (threadIdx.x == 0) found = 0;
    __syncthreads();
    int loc = 0;
    for (int i = threadIdx.x; i < Bc*Ec; i += blockDim.x)
        if ((i & 3) && raw[i]) loc = 1;
    if (loc) atomicOr(&found, 1);
    __syncthreads();
    if (threadIdx.x == 0) g_flag[0] = found ? 0 : 1;   // 1 => int32 layout
}

__global__ void canon_mask_kernel(const unsigned char* __restrict__ raw) {
    int i = blockIdx.x * blockDim.x + threadIdx.x;
    if (i < Bc*Ec) {
        if (g_flag[0]) g_mask[i] = (((const int*)raw)[i] != 0);
        else           g_mask[i] = (raw[i] != 0);
    }
}

// ---------------- SGEMM 128x128x8, 256 threads, 8x8 microtile ----------------
// MODE 1: C = A*W + bias + res      (row-major [M,N])
// MODE 2: C = gelu(A*W + bias)
// MODE 3: QKV scatter: C laid out [B,H,E,HD]
#define BM 128
#define BN 128
#define BK 8
#define TM 8
#define TN 8

__device__ __forceinline__ float gelu_exact(float v) {
    return 0.5f * v * (1.0f + erff(v * 0.70710678118654752f));
}

template<int MODE>
__global__ __launch_bounds__(256)
void sgemm_kernel(int M, int N, int K,
                  const float* __restrict__ A, const float* __restrict__ W,
                  const float* __restrict__ bias, const float* __restrict__ res,
                  float* __restrict__ C)
{
    __shared__ float As[BK][BM];
    __shared__ float Bs[BK][BN];
    const int tid = threadIdx.x;
    const int tr = tid / 16, tc = tid % 16;

    const int aRow = tid >> 1;            // 0..127
    const int aCol = (tid & 1) * 4;       // 0 or 4
    const int bRow = tid >> 5;            // 0..7
    const int bCol = (tid & 31) * 4;

    const float* Ab = A + (size_t)(blockIdx.y * BM) * K;
    const float* Bb = W + blockIdx.x * BN;

    float acc[TM][TN];
    #pragma unroll
    for (int i = 0; i < TM; i++)
        #pragma unroll
        for (int j = 0; j < TN; j++) acc[i][j] = 0.f;

    for (int k0 = 0; k0 < K; k0 += BK) {
        float4 a4 = *(const float4*)(Ab + (size_t)aRow * K + k0 + aCol);
        As[aCol + 0][aRow] = a4.x;
        As[aCol + 1][aRow] = a4.y;
        As[aCol + 2][aRow] = a4.z;
        As[aCol + 3][aRow] = a4.w;
        *(float4*)&Bs[bRow][bCol] = *(const float4*)(Bb + (size_t)(k0 + bRow) * N + bCol);
        __syncthreads();
        #pragma unroll
        for (int k = 0; k < BK; k++) {
            float ra[TM], rb[TN];
            #pragma unroll
            for (int i = 0; i < TM; i++) ra[i] = As[k][tr * TM + i];
            #pragma unroll
            for (int j = 0; j < TN; j++) rb[j] = Bs[k][tc * TN + j];
            #pragma unroll
            for (int i = 0; i < TM; i++)
                #pragma unroll
                for (int j = 0; j < TN; j++)
                    acc[i][j] += ra[i] * rb[j];
        }
        __syncthreads();
    }

    #pragma unroll
    for (int i = 0; i < TM; i++) {
        int row = blockIdx.y * BM + tr * TM + i;
        #pragma unroll
        for (int j = 0; j < TN; j++) {
            int col = blockIdx.x * BN + tc * TN + j;
            float v = acc[i][j] + bias[col];
            if (MODE == 1) {
                C[(size_t)row * N + col] = v + res[(size_t)row * N + col];
            } else if (MODE == 2) {
                C[(size_t)row * N + col] = gelu_exact(v);
            } else { // MODE 3: scatter to [B,H,E,HD]
                int b = row >> 10, e = row & 1023;
                int h = col >> 5,  hd = col & 31;
                C[((size_t)((b * Hc + h) * Ec + e)) * HDc + hd] = v;
            }
        }
    }
}

// ---------------- attention: thread-per-query, online softmax ----------------
#define TKEYS 64
__global__ __launch_bounds__(128)
void attn_kernel(const int* __restrict__ srel, const float* __restrict__ bias_emb)
{
    const int bh = blockIdx.x;           // 0..63
    const int b = bh / Hc, h = bh % Hc;
    const int qi = blockIdx.y * 128 + threadIdx.x;

    __shared__ float ks[TKEYS][HDc];
    __shared__ float vs[TKEYS][HDc];
    __shared__ int   msk[TKEYS];
    __shared__ float bsh[NBc * Hc];
    if (threadIdx.x < NBc * Hc) bsh[threadIdx.x] = bias_emb[threadIdx.x];

    float qr[HDc];
    {
        const float* qrow = g_q + ((size_t)bh * Ec + qi) * HDc;
        #pragma unroll
        for (int i = 0; i < 8; i++) {
            float4 t = *(const float4*)(qrow + i * 4);
            qr[i*4+0]=t.x; qr[i*4+1]=t.y; qr[i*4+2]=t.z; qr[i*4+3]=t.w;
        }
    }
    float m = -INFINITY, l = 0.f;
    float o[HDc];
    #pragma unroll
    for (int d = 0; d < HDc; d++) o[d] = 0.f;

    const int* srow = srel + ((size_t)b * Ec + qi) * Ec;

    for (int kt = 0; kt < Ec; kt += TKEYS) {
        __syncthreads();
        const float4* kb = (const float4*)(g_k + ((size_t)bh * Ec + kt) * HDc);
        const float4* vb = (const float4*)(g_v + ((size_t)bh * Ec + kt) * HDc);
        float4* ksd = (float4*)&ks[0][0];
        float4* vsd = (float4*)&vs[0][0];
        #pragma unroll
        for (int i = 0; i < 4; i++) {        // 512 float4 total over 128 threads
            ksd[threadIdx.x + i * 128] = kb[threadIdx.x + i * 128];
            vsd[threadIdx.x + i * 128] = vb[threadIdx.x + i * 128];
        }
        if (threadIdx.x < TKEYS) msk[threadIdx.x] = g_mask[b * Ec + kt + threadIdx.x];
        __syncthreads();

        for (int kk = 0; kk < TKEYS; kk++) {
            if (msk[kk]) continue;           // uniform across block
            float s = 0.f;
            #pragma unroll
            for (int d = 0; d < HDc; d++) s += qr[d] * ks[kk][d];
            s *= 0.17677669529663687f;       // 1/sqrt(32)
            s += bsh[__ldg(&srow[kt + kk]) * Hc + h];
            if (s > m) {
                float corr = __expf(m - s);  // exp(-inf)=0 on first key
                l *= corr;
                #pragma unroll
                for (int d = 0; d < HDc; d++) o[d] *= corr;
                m = s;
            }
            float p = __expf(s - m);
            l += p;
            #pragma unroll
            for (int d = 0; d < HDc; d++) o[d] += p * vs[kk][d];
        }
    }
    float inv = (l > 0.f) ? (1.f / l) : 0.f;
    float4* orow = (float4*)(g_attn + ((size_t)b * Ec + qi) * Dc + h * HDc);
    #pragma unroll
    for (int i = 0; i < 8; i++)
        orow[i] = make_float4(o[i*4]*inv, o[i*4+1]*inv, o[i*4+2]*inv, o[i*4+3]*inv);
}

// ---------------- LayerNorm: warp per row (D=256, 8 elems/lane) --------------
__global__ __launch_bounds__(256)
void ln_kernel(const float* __restrict__ x, const float* __restrict__ g,
               const float* __restrict__ be, float* __restrict__ y)
{
    int row = blockIdx.x * 8 + (threadIdx.x >> 5);
    int lane = threadIdx.x & 31;
    const float* xr = x + (size_t)row * Dc;
    float v[8], sum = 0.f;
    #pragma unroll
    for (int i = 0; i < 8; i++) { v[i] = xr[lane + i * 32]; sum += v[i]; }
    #pragma unroll
    for (int o = 16; o; o >>= 1) sum += __shfl_xor_sync(0xffffffff, sum, o);
    float mu = sum * (1.f / Dc);
    float var = 0.f;
    #pragma unroll
    for (int i = 0; i < 8; i++) { float d = v[i] - mu; var += d * d; }
    #pragma unroll
    for (int o = 16; o; o >>= 1) var += __shfl_xor_sync(0xffffffff, var, o);
    float rstd = rsqrtf(var * (1.f / Dc) + 1e-5f);
    float* yr = y + (size_t)row * Dc;
    #pragma unroll
    for (int i = 0; i < 8; i++) {
        int c = lane + i * 32;
        yr[c] = (v[i] - mu) * rstd * g[c] + be[c];
    }
}

// ---------------- launch ------------------------------------------------------
static float* sym(const void* s) { void* p = nullptr; cudaGetSymbolAddress(&p, s); return (float*)p; }

extern "C" void kernel_launch(void* const* d_in, const int* in_sizes, int n_in,
                              void* d_out, int out_size)
{
    const float* x    = (const float*)d_in[0];
    const int*   srel = (const int*)  d_in[1];
    const unsigned char* mraw = (const unsigned char*)d_in[2];
    const float* wq = (const float*)d_in[3];  const float* bq = (const float*)d_in[4];
    const float* wk = (const float*)d_in[5];  const float* bk = (const float*)d_in[6];
    const float* wv = (const float*)d_in[7];  const float* bv = (const float*)d_in[8];
    const float* wo = (const float*)d_in[9];  const float* bo = (const float*)d_in[10];
    const float* bias_emb = (const float*)d_in[11];
    const float* g1 = (const float*)d_in[12]; const float* be1 = (const float*)d_in[13];
    const float* w1 = (const float*)d_in[14]; const float* b1f = (const float*)d_in[15];
    const float* w2 = (const float*)d_in[16]; const float* b2f = (const float*)d_in[17];
    const float* g2 = (const float*)d_in[18]; const float* be2 = (const float*)d_in[19];
    float* out = (float*)d_out;

    float* q    = sym(g_q);
    float* k    = sym(g_k);
    float* v    = sym(g_v);
    float* attn = sym(g_attn);
    float* res1 = sym(g_res1);
    float* h1   = sym(g_h1);
    float* ff1  = sym(g_ff1);
    float* res2 = sym(g_res2);

    // mask canonicalization (robust to bool-as-u8 vs bool-as-i32)
    detect_mask_kernel<<<1, 256>>>(mraw);
    canon_mask_kernel<<<(Bc*Ec + 255) / 256, 256>>>(mraw);

    dim3 blk(256);
    // QKV projections -> [B,H,E,HD]
    {
        dim3 grid(Dc / BN, Mrows / BM);
        sgemm_kernel<3><<<grid, blk>>>(Mrows, Dc, Dc, x, wq, bq, nullptr, q);
        sgemm_kernel<3><<<grid, blk>>>(Mrows, Dc, Dc, x, wk, bk, nullptr, k);
        sgemm_kernel<3><<<grid, blk>>>(Mrows, Dc, Dc, x, wv, bv, nullptr, v);
    }
    // attention
    {
        dim3 grid(Bc * Hc, Ec / 128);
        attn_kernel<<<grid, 128>>>(srel, bias_emb);
    }
    // O projection + residual(x)
    {
        dim3 grid(Dc / BN, Mrows / BM);
        sgemm_kernel<1><<<grid, blk>>>(Mrows, Dc, Dc, attn, wo, bo, x, res1);
    }
    ln_kernel<<<Mrows / 8, 256>>>(res1, g1, be1, h1);
    // FFN
    {
        dim3 grid(FF / BN, Mrows / BM);
        sgemm_kernel<2><<<grid, blk>>>(Mrows, FF, Dc, h1, w1, b1f, nullptr, ff1);
    }
    {
        dim3 grid(Dc / BN, Mrows / BM);
        sgemm_kernel<1><<<grid, blk>>>(Mrows, Dc, FF, ff1, w2, b2f, h1, res2);
    }
    ln_kernel<<<Mrows / 8, 256>>>(res2, g2, be2, out);
}

// round 3
// speedup vs baseline: 1.4852x; 1.4852x over previous
#include <cuda_runtime.h>
#include <cuda_bf16.h>
#include <math.h>
#include <stdint.h>

#define Bc 8
#define Ec 1024
#define Dc 256
#define Hc 8
#define HDc 32
#define NBc 6
#define Mrows (Bc*Ec)   // 8192
#define FF (4*Dc)       // 1024

// ======================= scratch (device globals) ===========================
__device__ float g_q[Bc*Hc*Ec*HDc];     // [B,H,E,HD]
__device__ float g_k[Bc*Hc*Ec*HDc];
__device__ float g_v[Bc*Hc*Ec*HDc];
__device__ float g_res1[Mrows*Dc];
__device__ float g_h1[Mrows*Dc];
__device__ float g_res2[Mrows*Dc];
__device__ int   g_mask[Bc*Ec];
__device__ int   g_flag[1];

// split-bf16 activations
__device__ __nv_bfloat16 g_xhi[Mrows*Dc],  g_xlo[Mrows*Dc];
__device__ __nv_bfloat16 g_athi[Mrows*Dc], g_atlo[Mrows*Dc];
__device__ __nv_bfloat16 g_h1hi[Mrows*Dc], g_h1lo[Mrows*Dc];
__device__ __nv_bfloat16 g_f1hi[Mrows*FF], g_f1lo[Mrows*FF];
// split-bf16 transposed weights ([N,K] layout)
__device__ __nv_bfloat16 g_wqthi[Dc*Dc], g_wqtlo[Dc*Dc];
__device__ __nv_bfloat16 g_wkthi[Dc*Dc], g_wktlo[Dc*Dc];
__device__ __nv_bfloat16 g_wvthi[Dc*Dc], g_wvtlo[Dc*Dc];
__device__ __nv_bfloat16 g_wothi[Dc*Dc], g_wotlo[Dc*Dc];
__device__ __nv_bfloat16 g_w1thi[FF*Dc], g_w1tlo[FF*Dc];
__device__ __nv_bfloat16 g_w2thi[Dc*FF], g_w2tlo[Dc*FF];

// ======================= helpers ============================================
__device__ __forceinline__ uint32_t smem_u32(const void* p) {
    uint32_t a;
    asm("{ .reg .u64 t; cvta.to.shared.u64 t, %1; cvt.u32.u64 %0, t; }" : "=r"(a) : "l"(p));
    return a;
}
#define LDM_X4(r0,r1,r2,r3,addr) \
    asm volatile("ldmatrix.sync.aligned.m8n8.x4.shared.b16 {%0,%1,%2,%3}, [%4];" \
        : "=r"(r0),"=r"(r1),"=r"(r2),"=r"(r3) : "r"(addr))
#define LDM_X2(r0,r1,addr) \
    asm volatile("ldmatrix.sync.aligned.m8n8.x2.shared.b16 {%0,%1}, [%2];" \
        : "=r"(r0),"=r"(r1) : "r"(addr))
#define MMA_BF16(d,a,b) \
    asm volatile("mma.sync.aligned.m16n8k16.row.col.f32.bf16.bf16.f32 " \
        "{%0,%1,%2,%3}, {%4,%5,%6,%7}, {%8,%9}, {%0,%1,%2,%3};" \
        : "+f"((d)[0]),"+f"((d)[1]),"+f"((d)[2]),"+f"((d)[3]) \
        : "r"((a)[0]),"r"((a)[1]),"r"((a)[2]),"r"((a)[3]),"r"((b)[0]),"r"((b)[1]))

__device__ __forceinline__ float gelu_exact(float v) {
    return 0.5f * v * (1.0f + erff(v * 0.70710678118654752f));
}

// ======================= mask canonicalization ==============================
__global__ void detect_mask_kernel(const unsigned char* __restrict__ raw) {
    __shared__ int found;
    if (threadIdx.x == 0) found = 0;
    __syncthreads();
    int loc = 0;
    for (int i = threadIdx.x; i < Bc*Ec; i += blockDim.x)
        if ((i & 3) && raw[i]) loc = 1;
    if (loc) atomicOr(&found, 1);
    __syncthreads();
    if (threadIdx.x == 0) g_flag[0] = found ? 0 : 1;
}
__global__ void canon_mask_kernel(const unsigned char* __restrict__ raw) {
    int i = blockIdx.x * blockDim.x + threadIdx.x;
    if (i < Bc*Ec) {
        if (g_flag[0]) g_mask[i] = (((const int*)raw)[i] != 0);
        else           g_mask[i] = (raw[i] != 0);
    }
}

// ======================= split conversions ==================================
__global__ void split_kernel(const float* __restrict__ x,
                             __nv_bfloat16* __restrict__ hi, __nv_bfloat16* __restrict__ lo, int n) {
    int i = blockIdx.x * 256 + threadIdx.x;
    if (i < n) {
        float v = x[i];
        __nv_bfloat16 h = __float2bfloat16(v);
        hi[i] = h;
        lo[i] = __float2bfloat16(v - __bfloat162float(h));
    }
}
// W [K,N] fp32 -> Wt [N,K] split bf16
__global__ void wsplit_kernel(const float* __restrict__ W, int K, int N,
                              __nv_bfloat16* __restrict__ Thi, __nv_bfloat16* __restrict__ Tlo) {
    __shared__ float t[32][33];
    int n0 = blockIdx.x * 32, k0 = blockIdx.y * 32;
    for (int i = threadIdx.y; i < 32; i += 8)
        t[i][threadIdx.x] = W[(size_t)(k0 + i) * N + n0 + threadIdx.x];
    __syncthreads();
    for (int i = threadIdx.y; i < 32; i += 8) {
        float v = t[threadIdx.x][i];
        size_t o = (size_t)(n0 + i) * K + k0 + threadIdx.x;
        __nv_bfloat16 h = __float2bfloat16(v);
        Thi[o] = h;
        Tlo[o] = __float2bfloat16(v - __bfloat162float(h));
    }
}

// ======================= mma.sync split-bf16 GEMM ===========================
// D[m,n] = sum_k A[m,k]*B[n,k], A=[M,K] hi/lo, B=[N,K] hi/lo, fp32 accum.
// MODE 1: C = v + bias + res (fp32 [M,N])
// MODE 2: split-bf16 of gelu(v + bias) -> Chi/Clo (also needs N stride)
// MODE 3: v + bias scattered to [B,H,E,HD] fp32
#define PADg 40                       // row pitch (elems); 80B -> conflict-free ldmatrix
#define TILE_ELE (128*PADg)
#define SMEM_G (8*TILE_ELE*2)         // 2 stages x 4 tiles x 128x40 bf16 = 81920 B

__device__ __forceinline__ void load_stage_g(
    const __nv_bfloat16* const* src, int K, int kc,
    __nv_bfloat16* sm, int stage, int tid)
{
    #pragma unroll
    for (int t = 0; t < 4; t++) {
        __nv_bfloat16* dst = sm + (stage * 4 + t) * TILE_ELE;
        #pragma unroll
        for (int i = 0; i < 2; i++) {
            int idx = tid + i * 256;
            int row = idx >> 2, seg = idx & 3;
            uint32_t d = smem_u32(dst + row * PADg + seg * 8);
            const void* s = src[t] + (size_t)row * K + kc + seg * 8;
            asm volatile("cp.async.cg.shared.global [%0], [%1], 16;" :: "r"(d), "l"(s));
        }
    }
}

template<int MODE>
__global__ __launch_bounds__(256)
void mma_gemm(int M, int N, int K,
              const __nv_bfloat16* __restrict__ Ahi, const __nv_bfloat16* __restrict__ Alo,
              const __nv_bfloat16* __restrict__ Bhi, const __nv_bfloat16* __restrict__ Blo,
              const float* __restrict__ bias, const float* __restrict__ res,
              float* __restrict__ C,
              __nv_bfloat16* __restrict__ Chi, __nv_bfloat16* __restrict__ Clo)
{
    extern __shared__ __nv_bfloat16 smg[];
    const int tid = threadIdx.x, lane = tid & 31, wid = tid >> 5;
    const int wm = wid & 1, wn = wid >> 1;
    const int n0 = blockIdx.x * 128, m0 = blockIdx.y * 128;

    const __nv_bfloat16* src[4] = { Ahi + (size_t)m0 * K, Alo + (size_t)m0 * K,
                                    Bhi + (size_t)n0 * K, Blo + (size_t)n0 * K };

    float acc[4][4][4];
    #pragma unroll
    for (int a = 0; a < 4; a++)
        #pragma unroll
        for (int b = 0; b < 4; b++)
            #pragma unroll
            for (int c = 0; c < 4; c++) acc[a][b][c] = 0.f;

    const int NC = K / 32;
    load_stage_g(src, K, 0, smg, 0, tid);
    asm volatile("cp.async.commit_group;");

    for (int c = 0; c < NC; c++) {
        const int stage = c & 1;
        if (c + 1 < NC) {
            load_stage_g(src, K, (c + 1) * 32, smg, stage ^ 1, tid);
            asm volatile("cp.async.commit_group;");
            asm volatile("cp.async.wait_group 1;");
        } else {
            asm volatile("cp.async.wait_group 0;");
        }
        __syncthreads();

        const __nv_bfloat16* As_hi = smg + (stage * 4 + 0) * TILE_ELE;
        const __nv_bfloat16* As_lo = smg + (stage * 4 + 1) * TILE_ELE;
        const __nv_bfloat16* Bs_hi = smg + (stage * 4 + 2) * TILE_ELE;
        const __nv_bfloat16* Bs_lo = smg + (stage * 4 + 3) * TILE_ELE;

        #pragma unroll
        for (int k16 = 0; k16 < 2; k16++) {
            uint32_t ah[4][4], bh[4][2], bl[4][2];
            const int arow = wm * 64 + (lane & 15);
            const int acol = k16 * 16 + (lane >> 4) * 8;
            #pragma unroll
            for (int mt = 0; mt < 4; mt++) {
                uint32_t ad = smem_u32(As_hi + (arow + mt * 16) * PADg + acol);
                LDM_X4(ah[mt][0], ah[mt][1], ah[mt][2], ah[mt][3], ad);
            }
            const int brow = wn * 32 + (lane & 7);
            const int bcol = k16 * 16 + ((lane >> 3) & 1) * 8;
            #pragma unroll
            for (int nt = 0; nt < 4; nt++) {
                uint32_t bd = smem_u32(Bs_hi + (brow + nt * 8) * PADg + bcol);
                LDM_X2(bh[nt][0], bh[nt][1], bd);
                uint32_t bd2 = smem_u32(Bs_lo + (brow + nt * 8) * PADg + bcol);
                LDM_X2(bl[nt][0], bl[nt][1], bd2);
            }
            #pragma unroll
            for (int mt = 0; mt < 4; mt++)
                #pragma unroll
                for (int nt = 0; nt < 4; nt++) {
                    MMA_BF16(acc[mt][nt], ah[mt], bh[nt]);   // hi*hi
                    MMA_BF16(acc[mt][nt], ah[mt], bl[nt]);   // hi*lo
                }
            // A_lo over A_hi registers
            #pragma unroll
            for (int mt = 0; mt < 4; mt++) {
                uint32_t ad = smem_u32(As_lo + (arow + mt * 16) * PADg + acol);
                LDM_X4(ah[mt][0], ah[mt][1], ah[mt][2], ah[mt][3], ad);
            }
            #pragma unroll
            for (int mt = 0; mt < 4; mt++)
                #pragma unroll
                for (int nt = 0; nt < 4; nt++)
                    MMA_BF16(acc[mt][nt], ah[mt], bh[nt]);   // lo*hi
        }
        __syncthreads();
    }

    // ---- epilogue: direct float2 stores from accumulators ----
    #pragma unroll
    for (int mt = 0; mt < 4; mt++) {
        const int r0 = m0 + wm * 64 + mt * 16 + (lane >> 2);
        #pragma unroll
        for (int nt = 0; nt < 4; nt++) {
            const int gc = n0 + wn * 32 + nt * 8 + (lane & 3) * 2;
            const float b0 = bias[gc], b1 = bias[gc + 1];
            #pragma unroll
            for (int half = 0; half < 2; half++) {
                const int row = r0 + half * 8;
                float v0 = acc[mt][nt][half * 2 + 0] + b0;
                float v1 = acc[mt][nt][half * 2 + 1] + b1;
                if (MODE == 1) {
                    const float2 rr = *(const float2*)(res + (size_t)row * N + gc);
                    *(float2*)(C + (size_t)row * N + gc) = make_float2(v0 + rr.x, v1 + rr.y);
                } else if (MODE == 2) {
                    float gv0 = gelu_exact(v0), gv1 = gelu_exact(v1);
                    __nv_bfloat16 h0 = __float2bfloat16(gv0);
                    __nv_bfloat16 h1 = __float2bfloat16(gv1);
                    size_t o = (size_t)row * N + gc;
                    *(__nv_bfloat162*)(Chi + o) = __nv_bfloat162{h0, h1};
                    *(__nv_bfloat162*)(Clo + o) = __nv_bfloat162{
                        __float2bfloat16(gv0 - __bfloat162float(h0)),
                        __float2bfloat16(gv1 - __bfloat162float(h1))};
                } else { // MODE 3: scatter to [B,H,E,HD]
                    const int b = row >> 10, e = row & 1023;
                    const int h2 = gc >> 5, hd = gc & 31;
                    *(float2*)(C + ((size_t)((b * Hc + h2) * Ec + e)) * HDc + hd) =
                        make_float2(v0, v1);
                }
            }
        }
    }
}

// ======================= attention (fp32, thread-per-query) =================
#define TKEYS 64
__global__ __launch_bounds__(128)
void attn_kernel(const int* __restrict__ srel, const float* __restrict__ bias_emb)
{
    const int bh = blockIdx.x;
    const int b = bh / Hc, h = bh % Hc;
    const int qi = blockIdx.y * 128 + threadIdx.x;

    __shared__ float ks[TKEYS][HDc];
    __shared__ float vs[TKEYS][HDc];
    __shared__ int   msk[TKEYS];
    __shared__ float bsh[NBc * Hc];
    if (threadIdx.x < NBc * Hc) bsh[threadIdx.x] = bias_emb[threadIdx.x];

    float qr[HDc];
    {
        const float* qrow = g_q + ((size_t)bh * Ec + qi) * HDc;
        #pragma unroll
        for (int i = 0; i < 8; i++) {
            float4 t = *(const float4*)(qrow + i * 4);
            qr[i*4+0]=t.x; qr[i*4+1]=t.y; qr[i*4+2]=t.z; qr[i*4+3]=t.w;
        }
    }
    float m = -INFINITY, l = 0.f;
    float o[HDc];
    #pragma unroll
    for (int d = 0; d < HDc; d++) o[d] = 0.f;

    const int* srow = srel + ((size_t)b * Ec + qi) * Ec;

    for (int kt = 0; kt < Ec; kt += TKEYS) {
        __syncthreads();
        const float4* kb = (const float4*)(g_k + ((size_t)bh * Ec + kt) * HDc);
        const float4* vb = (const float4*)(g_v + ((size_t)bh * Ec + kt) * HDc);
        float4* ksd = (float4*)&ks[0][0];
        float4* vsd = (float4*)&vs[0][0];
        #pragma unroll
        for (int i = 0; i < 4; i++) {
            ksd[threadIdx.x + i * 128] = kb[threadIdx.x + i * 128];
            vsd[threadIdx.x + i * 128] = vb[threadIdx.x + i * 128];
        }
        if (threadIdx.x < TKEYS) msk[threadIdx.x] = g_mask[b * Ec + kt + threadIdx.x];
        __syncthreads();

        for (int kk = 0; kk < TKEYS; kk++) {
            if (msk[kk]) continue;
            float s = 0.f;
            #pragma unroll
            for (int d = 0; d < HDc; d++) s += qr[d] * ks[kk][d];
            s *= 0.17677669529663687f;
            s += bsh[__ldg(&srow[kt + kk]) * Hc + h];
            if (s > m) {
                float corr = __expf(m - s);
                l *= corr;
                #pragma unroll
                for (int d = 0; d < HDc; d++) o[d] *= corr;
                m = s;
            }
            float p = __expf(s - m);
            l += p;
            #pragma unroll
            for (int d = 0; d < HDc; d++) o[d] += p * vs[kk][d];
        }
    }
    float inv = (l > 0.f) ? (1.f / l) : 0.f;
    __nv_bfloat16* oh = g_athi + ((size_t)(b * Ec + qi)) * Dc + h * HDc;
    __nv_bfloat16* ol = g_atlo + ((size_t)(b * Ec + qi)) * Dc + h * HDc;
    #pragma unroll
    for (int d = 0; d < HDc; d++) {
        float val = o[d] * inv;
        __nv_bfloat16 hi = __float2bfloat16(val);
        oh[d] = hi;
        ol[d] = __float2bfloat16(val - __bfloat162float(hi));
    }
}

// ======================= LayerNorm ==========================================
__global__ __launch_bounds__(256)
void ln_kernel(const float* __restrict__ x, const float* __restrict__ g,
               const float* __restrict__ be, float* __restrict__ y,
               __nv_bfloat16* __restrict__ yhi, __nv_bfloat16* __restrict__ ylo)
{
    int row = blockIdx.x * 8 + (threadIdx.x >> 5);
    int lane = threadIdx.x & 31;
    const float* xr = x + (size_t)row * Dc;
    float v[8], sum = 0.f;
    #pragma unroll
    for (int i = 0; i < 8; i++) { v[i] = xr[lane + i * 32]; sum += v[i]; }
    #pragma unroll
    for (int o = 16; o; o >>= 1) sum += __shfl_xor_sync(0xffffffff, sum, o);
    float mu = sum * (1.f / Dc);
    float var = 0.f;
    #pragma unroll
    for (int i = 0; i < 8; i++) { float d = v[i] - mu; var += d * d; }
    #pragma unroll
    for (int o = 16; o; o >>= 1) var += __shfl_xor_sync(0xffffffff, var, o);
    float rstd = rsqrtf(var * (1.f / Dc) + 1e-5f);
    float* yr = y + (size_t)row * Dc;
    #pragma unroll
    for (int i = 0; i < 8; i++) {
        int c = lane + i * 32;
        float val = (v[i] - mu) * rstd * g[c] + be[c];
        yr[c] = val;
        if (yhi) {
            __nv_bfloat16 h = __float2bfloat16(val);
            yhi[(size_t)row * Dc + c] = h;
            ylo[(size_t)row * Dc + c] = __float2bfloat16(val - __bfloat162float(h));
        }
    }
}

// ======================= launch =============================================
static void* sym(const void* s) { void* p = nullptr; cudaGetSymbolAddress(&p, s); return p; }

extern "C" void kernel_launch(void* const* d_in, const int* in_sizes, int n_in,
                              void* d_out, int out_size)
{
    const float* x    = (const float*)d_in[0];
    const int*   srel = (const int*)  d_in[1];
    const unsigned char* mraw = (const unsigned char*)d_in[2];
    const float* wq = (const float*)d_in[3];  const float* bq = (const float*)d_in[4];
    const float* wk = (const float*)d_in[5];  const float* bk = (const float*)d_in[6];
    const float* wv = (const float*)d_in[7];  const float* bv = (const float*)d_in[8];
    const float* wo = (const float*)d_in[9];  const float* bo = (const float*)d_in[10];
    const float* bias_emb = (const float*)d_in[11];
    const float* g1 = (const float*)d_in[12]; const float* be1 = (const float*)d_in[13];
    const float* w1 = (const float*)d_in[14]; const float* b1f = (const float*)d_in[15];
    const float* w2 = (const float*)d_in[16]; const float* b2f = (const float*)d_in[17];
    const float* g2 = (const float*)d_in[18]; const float* be2 = (const float*)d_in[19];
    float* out = (float*)d_out;

    float* q    = (float*)sym(g_q);
    float* k    = (float*)sym(g_k);
    float* v    = (float*)sym(g_v);
    float* res1 = (float*)sym(g_res1);
    float* h1   = (float*)sym(g_h1);
    float* res2 = (float*)sym(g_res2);
    __nv_bfloat16* xhi  = (__nv_bfloat16*)sym(g_xhi);
    __nv_bfloat16* xlo  = (__nv_bfloat16*)sym(g_xlo);
    __nv_bfloat16* athi = (__nv_bfloat16*)sym(g_athi);
    __nv_bfloat16* atlo = (__nv_bfloat16*)sym(g_atlo);
    __nv_bfloat16* h1hi = (__nv_bfloat16*)sym(g_h1hi);
    __nv_bfloat16* h1lo = (__nv_bfloat16*)sym(g_h1lo);
    __nv_bfloat16* f1hi = (__nv_bfloat16*)sym(g_f1hi);
    __nv_bfloat16* f1lo = (__nv_bfloat16*)sym(g_f1lo);
    __nv_bfloat16* wqthi = (__nv_bfloat16*)sym(g_wqthi); __nv_bfloat16* wqtlo = (__nv_bfloat16*)sym(g_wqtlo);
    __nv_bfloat16* wkthi = (__nv_bfloat16*)sym(g_wkthi); __nv_bfloat16* wktlo = (__nv_bfloat16*)sym(g_wktlo);
    __nv_bfloat16* wvthi = (__nv_bfloat16*)sym(g_wvthi); __nv_bfloat16* wvtlo = (__nv_bfloat16*)sym(g_wvtlo);
    __nv_bfloat16* wothi = (__nv_bfloat16*)sym(g_wothi); __nv_bfloat16* wotlo = (__nv_bfloat16*)sym(g_wotlo);
    __nv_bfloat16* w1thi = (__nv_bfloat16*)sym(g_w1thi); __nv_bfloat16* w1tlo = (__nv_bfloat16*)sym(g_w1tlo);
    __nv_bfloat16* w2thi = (__nv_bfloat16*)sym(g_w2thi); __nv_bfloat16* w2tlo = (__nv_bfloat16*)sym(g_w2tlo);

    cudaFuncSetAttribute(mma_gemm<1>, cudaFuncAttributeMaxDynamicSharedMemorySize, SMEM_G);
    cudaFuncSetAttribute(mma_gemm<2>, cudaFuncAttributeMaxDynamicSharedMemorySize, SMEM_G);
    cudaFuncSetAttribute(mma_gemm<3>, cudaFuncAttributeMaxDynamicSharedMemorySize, SMEM_G);

    // mask canonicalization
    detect_mask_kernel<<<1, 256>>>(mraw);
    canon_mask_kernel<<<(Bc*Ec + 255) / 256, 256>>>(mraw);

    // input split + weight transpose/split
    split_kernel<<<(Mrows*Dc + 255) / 256, 256>>>(x, xhi, xlo, Mrows*Dc);
    {
        dim3 b32(32, 8);
        wsplit_kernel<<<dim3(Dc/32, Dc/32), b32>>>(wq, Dc, Dc, wqthi, wqtlo);
        wsplit_kernel<<<dim3(Dc/32, Dc/32), b32>>>(wk, Dc, Dc, wkthi, wktlo);
        wsplit_kernel<<<dim3(Dc/32, Dc/32), b32>>>(wv, Dc, Dc, wvthi, wvtlo);
        wsplit_kernel<<<dim3(Dc/32, Dc/32), b32>>>(wo, Dc, Dc, wothi, wotlo);
        wsplit_kernel<<<dim3(FF/32, Dc/32), b32>>>(w1, Dc, FF, w1thi, w1tlo);  // [D,4D] -> [4D,D]
        wsplit_kernel<<<dim3(Dc/32, FF/32), b32>>>(w2, FF, Dc, w2thi, w2tlo);  // [4D,D] -> [D,4D]
    }

    // QKV projections -> [B,H,E,HD] fp32
    {
        dim3 grid(Dc/128, Mrows/128);
        mma_gemm<3><<<grid, 256, SMEM_G>>>(Mrows, Dc, Dc, xhi, xlo, wqthi, wqtlo, bq, nullptr, q, nullptr, nullptr);
        mma_gemm<3><<<grid, 256, SMEM_G>>>(Mrows, Dc, Dc, xhi, xlo, wkthi, wktlo, bk, nullptr, k, nullptr, nullptr);
        mma_gemm<3><<<grid, 256, SMEM_G>>>(Mrows, Dc, Dc, xhi, xlo, wvthi, wvtlo, bv, nullptr, v, nullptr, nullptr);
    }
    // attention -> split bf16 attn output [B,E,D]
    attn_kernel<<<dim3(Bc*Hc, Ec/128), 128>>>(srel, bias_emb);
    // O projection + residual(x)
    mma_gemm<1><<<dim3(Dc/128, Mrows/128), 256, SMEM_G>>>(Mrows, Dc, Dc, athi, atlo, wothi, wotlo, bo, x, res1, nullptr, nullptr);
    ln_kernel<<<Mrows/8, 256>>>(res1, g1, be1, h1, h1hi, h1lo);
    // FFN
    mma_gemm<2><<<dim3(FF/128, Mrows/128), 256, SMEM_G>>>(Mrows, FF, Dc, h1hi, h1lo, w1thi, w1tlo, b1f, nullptr, nullptr, f1hi, f1lo);
    mma_gemm<1><<<dim3(Dc/128, Mrows/128), 256, SMEM_G>>>(Mrows, Dc, FF, f1hi, f1lo, w2thi, w2tlo, b2f, h1, res2, nullptr, nullptr);
    ln_kernel<<<Mrows/8, 256>>>(res2, g2, be2, out, nullptr, nullptr);
}

// round 5
// speedup vs baseline: 2.4781x; 1.6686x over previous
#include <cuda_runtime.h>
#include <cuda_bf16.h>
#include <math.h>
#include <stdint.h>

#define Bc 8
#define Ec 1024
#define Dc 256
#define Hc 8
#define HDc 32
#define NBc 6
#define Mrows (Bc*Ec)   // 8192
#define FF (4*Dc)       // 1024

// ======================= scratch (device globals) ===========================
__device__ float g_res1[Mrows*Dc];
__device__ float g_h1[Mrows*Dc];
__device__ float g_res2[Mrows*Dc];
__device__ int   g_mask[Bc*Ec];
__device__ int   g_flag[1];
__device__ int   g_bflag[1];
__device__ __nv_bfloat16 g_ones[Bc*Ec];

// split-bf16 activations
__device__ __nv_bfloat16 g_xhi[Mrows*Dc],  g_xlo[Mrows*Dc];
__device__ __nv_bfloat16 g_qhi[Mrows*Dc],  g_qlo[Mrows*Dc];   // [B,H,E,HD]
__device__ __nv_bfloat16 g_khi[Mrows*Dc],  g_klo[Mrows*Dc];   // [B,H,E,HD]
__device__ __nv_bfloat16 g_vthi[Mrows*Dc], g_vtlo[Mrows*Dc];  // [B,H,HD,E]
__device__ __nv_bfloat16 g_athi[Mrows*Dc], g_atlo[Mrows*Dc];  // [B,E,D]
__device__ __nv_bfloat16 g_h1hi[Mrows*Dc], g_h1lo[Mrows*Dc];
__device__ __nv_bfloat16 g_f1hi[Mrows*FF], g_f1lo[Mrows*FF];
// split-bf16 transposed weights ([N,K] layout)
__device__ __nv_bfloat16 g_wqthi[Dc*Dc], g_wqtlo[Dc*Dc];
__device__ __nv_bfloat16 g_wkthi[Dc*Dc], g_wktlo[Dc*Dc];
__device__ __nv_bfloat16 g_wvthi[Dc*Dc], g_wvtlo[Dc*Dc];
__device__ __nv_bfloat16 g_wothi[Dc*Dc], g_wotlo[Dc*Dc];
__device__ __nv_bfloat16 g_w1thi[FF*Dc], g_w1tlo[FF*Dc];
__device__ __nv_bfloat16 g_w2thi[Dc*FF], g_w2tlo[Dc*FF];

// ======================= helpers ============================================
__device__ __forceinline__ uint32_t smem_u32(const void* p) {
    uint32_t a;
    asm("{ .reg .u64 t; cvta.to.shared.u64 t, %1; cvt.u32.u64 %0, t; }" : "=r"(a) : "l"(p));
    return a;
}
__device__ __forceinline__ void cpa16(uint32_t d, const void* s) {
    asm volatile("cp.async.cg.shared.global [%0], [%1], 16;" :: "r"(d), "l"(s));
}
#define LDM_X4(r0,r1,r2,r3,addr) \
    asm volatile("ldmatrix.sync.aligned.m8n8.x4.shared.b16 {%0,%1,%2,%3}, [%4];" \
        : "=r"(r0),"=r"(r1),"=r"(r2),"=r"(r3) : "r"(addr))
#define LDM_X2(r0,r1,addr) \
    asm volatile("ldmatrix.sync.aligned.m8n8.x2.shared.b16 {%0,%1}, [%2];" \
        : "=r"(r0),"=r"(r1) : "r"(addr))
#define MMA_BF16(d,a,b) \
    asm volatile("mma.sync.aligned.m16n8k16.row.col.f32.bf16.bf16.f32 " \
        "{%0,%1,%2,%3}, {%4,%5,%6,%7}, {%8,%9}, {%0,%1,%2,%3};" \
        : "+f"((d)[0]),"+f"((d)[1]),"+f"((d)[2]),"+f"((d)[3]) \
        : "r"((a)[0]),"r"((a)[1]),"r"((a)[2]),"r"((a)[3]),"r"((b)[0]),"r"((b)[1]))

__device__ __forceinline__ float gelu_exact(float v) {
    return 0.5f * v * (1.0f + erff(v * 0.70710678118654752f));
}
__device__ __forceinline__ uint32_t pack_bf16(float a, float b) {
    __nv_bfloat162 t = __floats2bfloat162_rn(a, b);
    return *(uint32_t*)&t;
}

// ======================= small prep kernels =================================
__global__ void detect_mask_kernel(const unsigned char* __restrict__ raw) {
    __shared__ int found;
    if (threadIdx.x == 0) found = 0;
    __syncthreads();
    int loc = 0;
    for (int i = threadIdx.x; i < Bc*Ec; i += blockDim.x)
        if ((i & 3) && raw[i]) loc = 1;
    if (loc) atomicOr(&found, 1);
    __syncthreads();
    if (threadIdx.x == 0) g_flag[0] = found ? 0 : 1;
}
__global__ void canon_mask_kernel(const unsigned char* __restrict__ raw) {
    int i = blockIdx.x * blockDim.x + threadIdx.x;
    if (i < Bc*Ec) {
        int m;
        if (g_flag[0]) m = (((const int*)raw)[i] != 0);
        else           m = (raw[i] != 0);
        g_mask[i] = m;
        g_ones[i] = __float2bfloat16(m ? 0.f : 1.f);
    }
}
__global__ void detect_bias_kernel(const float* __restrict__ be) {
    __shared__ int f;
    if (threadIdx.x == 0) f = 0;
    __syncthreads();
    if (threadIdx.x < NBc*Hc && be[threadIdx.x] != 0.f) atomicOr(&f, 1);
    __syncthreads();
    if (threadIdx.x == 0) g_bflag[0] = f;
}

// ======================= split conversions ==================================
__global__ void split_kernel(const float* __restrict__ x,
                             __nv_bfloat16* __restrict__ hi, __nv_bfloat16* __restrict__ lo, int n) {
    int i = blockIdx.x * 256 + threadIdx.x;
    if (i < n) {
        float v = x[i];
        __nv_bfloat16 h = __float2bfloat16(v);
        hi[i] = h;
        lo[i] = __float2bfloat16(v - __bfloat162float(h));
    }
}
__global__ void wsplit_kernel(const float* __restrict__ W, int K, int N,
                              __nv_bfloat16* __restrict__ Thi, __nv_bfloat16* __restrict__ Tlo) {
    __shared__ float t[32][33];
    int n0 = blockIdx.x * 32, k0 = blockIdx.y * 32;
    for (int i = threadIdx.y; i < 32; i += 8)
        t[i][threadIdx.x] = W[(size_t)(k0 + i) * N + n0 + threadIdx.x];
    __syncthreads();
    for (int i = threadIdx.y; i < 32; i += 8) {
        float v = t[threadIdx.x][i];
        size_t o = (size_t)(n0 + i) * K + k0 + threadIdx.x;
        __nv_bfloat16 h = __float2bfloat16(v);
        Thi[o] = h;
        Tlo[o] = __float2bfloat16(v - __bfloat162float(h));
    }
}

// ======================= mma.sync split-bf16 GEMM ===========================
// MODE 1: C = v + bias + res (fp32 [M,N])
// MODE 2: split-bf16 of gelu(v + bias) -> Chi/Clo
// MODE 4: split-bf16 of (v+bias)*scl scattered to [B,H,E,HD]
// MODE 6: split-bf16 of (v+bias), mask-zeroed, scattered to [B,H,HD,E]
#define PADg 40
#define TILE_ELE (128*PADg)
#define SMEM_G (8*TILE_ELE*2)

__device__ __forceinline__ void load_stage_g(
    const __nv_bfloat16* const* src, int K, int kc,
    __nv_bfloat16* sm, int stage, int tid)
{
    #pragma unroll
    for (int t = 0; t < 4; t++) {
        __nv_bfloat16* dst = sm + (stage * 4 + t) * TILE_ELE;
        #pragma unroll
        for (int i = 0; i < 2; i++) {
            int idx = tid + i * 256;
            int row = idx >> 2, seg = idx & 3;
            cpa16(smem_u32(dst + row * PADg + seg * 8),
                  src[t] + (size_t)row * K + kc + seg * 8);
        }
    }
}

template<int MODE>
__global__ __launch_bounds__(256)
void mma_gemm(int M, int N, int K,
              const __nv_bfloat16* __restrict__ Ahi, const __nv_bfloat16* __restrict__ Alo,
              const __nv_bfloat16* __restrict__ Bhi, const __nv_bfloat16* __restrict__ Blo,
              const float* __restrict__ bias, const float* __restrict__ res,
              float* __restrict__ C,
              __nv_bfloat16* __restrict__ Chi, __nv_bfloat16* __restrict__ Clo,
              float scl)
{
    extern __shared__ __nv_bfloat16 smg[];
    const int tid = threadIdx.x, lane = tid & 31, wid = tid >> 5;
    const int wm = wid & 1, wn = wid >> 1;
    const int n0 = blockIdx.x * 128, m0 = blockIdx.y * 128;

    const __nv_bfloat16* src[4] = { Ahi + (size_t)m0 * K, Alo + (size_t)m0 * K,
                                    Bhi + (size_t)n0 * K, Blo + (size_t)n0 * K };

    float acc[4][4][4];
    #pragma unroll
    for (int a = 0; a < 4; a++)
        #pragma unroll
        for (int b = 0; b < 4; b++)
            #pragma unroll
            for (int c = 0; c < 4; c++) acc[a][b][c] = 0.f;

    const int NC = K / 32;
    load_stage_g(src, K, 0, smg, 0, tid);
    asm volatile("cp.async.commit_group;");

    for (int c = 0; c < NC; c++) {
        const int stage = c & 1;
        if (c + 1 < NC) {
            load_stage_g(src, K, (c + 1) * 32, smg, stage ^ 1, tid);
            asm volatile("cp.async.commit_group;");
            asm volatile("cp.async.wait_group 1;");
        } else {
            asm volatile("cp.async.wait_group 0;");
        }
        __syncthreads();

        const __nv_bfloat16* As_hi = smg + (stage * 4 + 0) * TILE_ELE;
        const __nv_bfloat16* As_lo = smg + (stage * 4 + 1) * TILE_ELE;
        const __nv_bfloat16* Bs_hi = smg + (stage * 4 + 2) * TILE_ELE;
        const __nv_bfloat16* Bs_lo = smg + (stage * 4 + 3) * TILE_ELE;

        #pragma unroll
        for (int k16 = 0; k16 < 2; k16++) {
            uint32_t ah[4][4], bh[4][2], bl[4][2];
            const int arow = wm * 64 + (lane & 15);
            const int acol = k16 * 16 + (lane >> 4) * 8;
            #pragma unroll
            for (int mt = 0; mt < 4; mt++) {
                uint32_t ad = smem_u32(As_hi + (arow + mt * 16) * PADg + acol);
                LDM_X4(ah[mt][0], ah[mt][1], ah[mt][2], ah[mt][3], ad);
            }
            const int brow = wn * 32 + (lane & 7);
            const int bcol = k16 * 16 + ((lane >> 3) & 1) * 8;
            #pragma unroll
            for (int nt = 0; nt < 4; nt++) {
                LDM_X2(bh[nt][0], bh[nt][1], smem_u32(Bs_hi + (brow + nt * 8) * PADg + bcol));
                LDM_X2(bl[nt][0], bl[nt][1], smem_u32(Bs_lo + (brow + nt * 8) * PADg + bcol));
            }
            #pragma unroll
            for (int mt = 0; mt < 4; mt++)
                #pragma unroll
                for (int nt = 0; nt < 4; nt++) {
                    MMA_BF16(acc[mt][nt], ah[mt], bh[nt]);
                    MMA_BF16(acc[mt][nt], ah[mt], bl[nt]);
                }
            #pragma unroll
            for (int mt = 0; mt < 4; mt++) {
                uint32_t ad = smem_u32(As_lo + (arow + mt * 16) * PADg + acol);
                LDM_X4(ah[mt][0], ah[mt][1], ah[mt][2], ah[mt][3], ad);
            }
            #pragma unroll
            for (int mt = 0; mt < 4; mt++)
                #pragma unroll
                for (int nt = 0; nt < 4; nt++)
                    MMA_BF16(acc[mt][nt], ah[mt], bh[nt]);
        }
        __syncthreads();
    }

    #pragma unroll
    for (int mt = 0; mt < 4; mt++) {
        const int r0 = m0 + wm * 64 + mt * 16 + (lane >> 2);
        #pragma unroll
        for (int nt = 0; nt < 4; nt++) {
            const int gc = n0 + wn * 32 + nt * 8 + (lane & 3) * 2;
            const float b0 = bias[gc], b1 = bias[gc + 1];
            #pragma unroll
            for (int half = 0; half < 2; half++) {
                const int row = r0 + half * 8;
                float v0 = acc[mt][nt][half * 2 + 0] + b0;
                float v1 = acc[mt][nt][half * 2 + 1] + b1;
                if (MODE == 1) {
                    const float2 rr = *(const float2*)(res + (size_t)row * N + gc);
                    *(float2*)(C + (size_t)row * N + gc) = make_float2(v0 + rr.x, v1 + rr.y);
                } else if (MODE == 2) {
                    float gv0 = gelu_exact(v0), gv1 = gelu_exact(v1);
                    __nv_bfloat16 h0 = __float2bfloat16(gv0), h1 = __float2bfloat16(gv1);
                    size_t o = (size_t)row * N + gc;
                    *(__nv_bfloat162*)(Chi + o) = __nv_bfloat162{h0, h1};
                    *(__nv_bfloat162*)(Clo + o) = __nv_bfloat162{
                        __float2bfloat16(gv0 - __bfloat162float(h0)),
                        __float2bfloat16(gv1 - __bfloat162float(h1))};
                } else if (MODE == 4) {
                    float s0 = v0 * scl, s1 = v1 * scl;
                    __nv_bfloat16 h0 = __float2bfloat16(s0), h1 = __float2bfloat16(s1);
                    const int bb = row >> 10, e = row & 1023;
                    const int h2 = gc >> 5, hd = gc & 31;
                    size_t o = (((size_t)(bb * Hc + h2) * Ec + e)) * HDc + hd;
                    *(__nv_bfloat162*)(Chi + o) = __nv_bfloat162{h0, h1};
                    *(__nv_bfloat162*)(Clo + o) = __nv_bfloat162{
                        __float2bfloat16(s0 - __bfloat162float(h0)),
                        __float2bfloat16(s1 - __bfloat162float(h1))};
                } else { // MODE 6: V^T with mask zeroing
                    const int bb = row >> 10, e = row & 1023;
                    const int h2 = gc >> 5, hd = gc & 31;
                    if (g_mask[bb * Ec + e]) { v0 = 0.f; v1 = 0.f; }
                    size_t o = (((size_t)(bb * Hc + h2) * HDc + hd)) * Ec + e;
                    __nv_bfloat16 h0 = __float2bfloat16(v0), h1 = __float2bfloat16(v1);
                    Chi[o] = h0; Chi[o + Ec] = h1;
                    Clo[o]      = __float2bfloat16(v0 - __bfloat162float(h0));
                    Clo[o + Ec] = __float2bfloat16(v1 - __bfloat162float(h1));
                }
            }
        }
    }
}

// ======================= MMA FlashAttention =================================
// V^T tile pitch: 136 elems = 272 B (16B-aligned; 272%128==16 -> conflict-free)
#define VP 136
#define VTILE_B (40*272)      // 10880 B per V buffer (40 rows: 32 V + ones + pad)
#define AT_Q   0
#define AT_QL  10240
#define AT_K(s)  (20480 + (s)*10240)
#define AT_KL(s) (40960 + (s)*10240)
#define AT_V(s)  (61440 + (s)*VTILE_B)
#define AT_VL(s) (61440 + 2*VTILE_B + (s)*VTILE_B)
#define AT_BSH   (61440 + 4*VTILE_B)
#define AT_SMEM  (AT_BSH + 256)

__global__ __launch_bounds__(256)
void attn_mma(const int* __restrict__ srel, const float* __restrict__ bias_emb)
{
    extern __shared__ char sm[];
    const uint32_t sb = smem_u32(sm);
    const int tid = threadIdx.x, lane = tid & 31, wid = tid >> 5;
    const int bh = blockIdx.x, qt = blockIdx.y;
    const int b = bh >> 3, h = bh & 7;
    const int bias_nz = g_bflag[0];

    if (tid < NBc*Hc) ((float*)(sm + AT_BSH))[tid] = bias_emb[tid];

    // zero V pad rows 32..39 (both stages, hi+lo); ones row (hi, row 32) overwritten by cp.async
    for (int i = tid; i < 4 * 544; i += 256) {
        int buf = i / 544, off = i % 544;
        uint32_t base = (buf & 1) ? AT_VL(buf >> 1) : AT_V(buf >> 1);
        *(uint32_t*)(sm + base + 32 * 272 + off * 4) = 0;
    }

    const __nv_bfloat16* qhi = g_qhi + ((size_t)bh * Ec + qt * 128) * HDc;
    const __nv_bfloat16* qlo = g_qlo + ((size_t)bh * Ec + qt * 128) * HDc;

    #pragma unroll
    for (int i = 0; i < 2; i++) {
        int idx = tid + i * 256, r = idx >> 2, sg = idx & 3;
        cpa16(sb + AT_Q  + r * 80 + sg * 16, qhi + r * HDc + sg * 8);
        cpa16(sb + AT_QL + r * 80 + sg * 16, qlo + r * HDc + sg * 8);
    }
    {
        const __nv_bfloat16* khi = g_khi + (size_t)bh * Ec * HDc;
        const __nv_bfloat16* klo = g_klo + (size_t)bh * Ec * HDc;
        const __nv_bfloat16* vhi = g_vthi + (size_t)bh * HDc * Ec;
        const __nv_bfloat16* vlo = g_vtlo + (size_t)bh * HDc * Ec;
        #pragma unroll
        for (int i = 0; i < 2; i++) {
            int idx = tid + i * 256, r = idx >> 2, sg = idx & 3;
            cpa16(sb + AT_K(0)  + r * 80 + sg * 16, khi + r * HDc + sg * 8);
            cpa16(sb + AT_KL(0) + r * 80 + sg * 16, klo + r * HDc + sg * 8);
        }
        #pragma unroll
        for (int i = 0; i < 2; i++) {
            int idx = tid + i * 256, r = idx >> 4, sg = idx & 15;
            cpa16(sb + AT_V(0)  + r * 272 + sg * 16, vhi + (size_t)r * Ec + sg * 8);
            cpa16(sb + AT_VL(0) + r * 272 + sg * 16, vlo + (size_t)r * Ec + sg * 8);
        }
        if (tid < 16) cpa16(sb + AT_V(0) + 32 * 272 + tid * 16, g_ones + b * Ec + tid * 8);
    }
    asm volatile("cp.async.commit_group;");

    float m0 = -INFINITY, m1 = -INFINITY;
    float o[5][4];
    #pragma unroll
    for (int nv = 0; nv < 5; nv++)
        #pragma unroll
        for (int j = 0; j < 4; j++) o[nv][j] = 0.f;
    uint32_t qfh[2][4], qfl[2][4];

    for (int c = 0; c < 8; c++) {
        const int st = c & 1;
        const int kt = c * 128;
        if (c < 7) {
            const int ktn = kt + 128;
            const __nv_bfloat16* khi = g_khi + ((size_t)bh * Ec + ktn) * HDc;
            const __nv_bfloat16* klo = g_klo + ((size_t)bh * Ec + ktn) * HDc;
            const __nv_bfloat16* vhi = g_vthi + (size_t)bh * HDc * Ec + ktn;
            const __nv_bfloat16* vlo = g_vtlo + (size_t)bh * HDc * Ec + ktn;
            #pragma unroll
            for (int i = 0; i < 2; i++) {
                int idx = tid + i * 256, r = idx >> 2, sg = idx & 3;
                cpa16(sb + AT_K(st ^ 1)  + r * 80 + sg * 16, khi + r * HDc + sg * 8);
                cpa16(sb + AT_KL(st ^ 1) + r * 80 + sg * 16, klo + r * HDc + sg * 8);
            }
            #pragma unroll
            for (int i = 0; i < 2; i++) {
                int idx = tid + i * 256, r = idx >> 4, sg = idx & 15;
                cpa16(sb + AT_V(st ^ 1)  + r * 272 + sg * 16, vhi + (size_t)r * Ec + sg * 8);
                cpa16(sb + AT_VL(st ^ 1) + r * 272 + sg * 16, vlo + (size_t)r * Ec + sg * 8);
            }
            if (tid < 16) cpa16(sb + AT_V(st ^ 1) + 32 * 272 + tid * 16, g_ones + b * Ec + ktn + tid * 8);
            asm volatile("cp.async.commit_group;");
            asm volatile("cp.async.wait_group 1;");
        } else {
            asm volatile("cp.async.wait_group 0;");
        }
        __syncthreads();

        if (c == 0) {
            const int arow = wid * 16 + (lane & 15);
            const int acsel = (lane >> 4) * 8;
            #pragma unroll
            for (int k16 = 0; k16 < 2; k16++) {
                LDM_X4(qfh[k16][0], qfh[k16][1], qfh[k16][2], qfh[k16][3],
                       sb + AT_Q  + (arow * PADg + k16 * 16 + acsel) * 2);
                LDM_X4(qfl[k16][0], qfl[k16][1], qfl[k16][2], qfl[k16][3],
                       sb + AT_QL + (arow * PADg + k16 * 16 + acsel) * 2);
            }
        }

        // ---- S = Q K^T ----
        float s[16][4];
        #pragma unroll
        for (int f = 0; f < 16; f++)
            #pragma unroll
            for (int j = 0; j < 4; j++) s[f][j] = 0.f;

        {
            const int krow = (lane & 15);
            const int kcsel = (lane >> 4) * 8;
            #pragma unroll
            for (int nt16 = 0; nt16 < 8; nt16++) {
                #pragma unroll
                for (int k16 = 0; k16 < 2; k16++) {
                    uint32_t h0,h1,h2,h3, l0,l1,l2,l3;
                    LDM_X4(h0,h1,h2,h3, sb + AT_K(st)  + ((nt16*16 + krow) * PADg + k16*16 + kcsel) * 2);
                    LDM_X4(l0,l1,l2,l3, sb + AT_KL(st) + ((nt16*16 + krow) * PADg + k16*16 + kcsel) * 2);
                    uint32_t bh0[2] = {h0, h2}, bh1[2] = {h1, h3};
                    uint32_t bl0[2] = {l0, l2}, bl1[2] = {l1, l3};
                    MMA_BF16(s[2*nt16],   qfh[k16], bh0);
                    MMA_BF16(s[2*nt16],   qfh[k16], bl0);
                    MMA_BF16(s[2*nt16],   qfl[k16], bh0);
                    MMA_BF16(s[2*nt16+1], qfh[k16], bh1);
                    MMA_BF16(s[2*nt16+1], qfh[k16], bl1);
                    MMA_BF16(s[2*nt16+1], qfl[k16], bh1);
                }
            }
        }

        // ---- optional learned relative bias (dataset has zeros) ----
        if (bias_nz) {
            const float* bsh = (const float*)(sm + AT_BSH);
            const int q0 = qt * 128 + wid * 16 + (lane >> 2);
            #pragma unroll
            for (int f = 0; f < 16; f++) {
                const int key = kt + f * 8 + (lane & 3) * 2;
                const int* r0 = srel + ((size_t)b * Ec + q0) * Ec + key;
                const int* r1 = srel + ((size_t)b * Ec + q0 + 8) * Ec + key;
                s[f][0] += bsh[__ldg(r0)     * Hc + h];
                s[f][1] += bsh[__ldg(r0 + 1) * Hc + h];
                s[f][2] += bsh[__ldg(r1)     * Hc + h];
                s[f][3] += bsh[__ldg(r1 + 1) * Hc + h];
            }
        }

        // ---- online softmax (masked keys have zeroed V cols & ones) ----
        float t0 = -INFINITY, t1 = -INFINITY;
        #pragma unroll
        for (int f = 0; f < 16; f++) {
            t0 = fmaxf(t0, fmaxf(s[f][0], s[f][1]));
            t1 = fmaxf(t1, fmaxf(s[f][2], s[f][3]));
        }
        t0 = fmaxf(t0, __shfl_xor_sync(0xffffffff, t0, 1));
        t0 = fmaxf(t0, __shfl_xor_sync(0xffffffff, t0, 2));
        t1 = fmaxf(t1, __shfl_xor_sync(0xffffffff, t1, 1));
        t1 = fmaxf(t1, __shfl_xor_sync(0xffffffff, t1, 2));
        const float mn0 = fmaxf(m0, t0), mn1 = fmaxf(m1, t1);
        const float cor0 = __expf(m0 - mn0), cor1 = __expf(m1 - mn1);
        m0 = mn0; m1 = mn1;
        #pragma unroll
        for (int nv = 0; nv < 5; nv++) {
            o[nv][0] *= cor0; o[nv][1] *= cor0;
            o[nv][2] *= cor1; o[nv][3] *= cor1;
        }
        uint32_t ph[16][2], pl[16][2];
        #pragma unroll
        for (int f = 0; f < 16; f++) {
            float p0 = __expf(s[f][0] - m0), p1 = __expf(s[f][1] - m0);
            float p2 = __expf(s[f][2] - m1), p3 = __expf(s[f][3] - m1);
            ph[f][0] = pack_bf16(p0, p1);
            ph[f][1] = pack_bf16(p2, p3);
            __nv_bfloat162 h01 = *(__nv_bfloat162*)&ph[f][0];
            __nv_bfloat162 h23 = *(__nv_bfloat162*)&ph[f][1];
            pl[f][0] = pack_bf16(p0 - __bfloat162float(h01.x), p1 - __bfloat162float(h01.y));
            pl[f][1] = pack_bf16(p2 - __bfloat162float(h23.x), p3 - __bfloat162float(h23.y));
        }

        // ---- O += P V ----
        {
            const int vrow = (lane & 7);
            const int vcsel = ((lane >> 3) & 1) * 8;
            #pragma unroll
            for (int j = 0; j < 8; j++) {
                uint32_t ahh[4] = {ph[2*j][0], ph[2*j][1], ph[2*j+1][0], ph[2*j+1][1]};
                uint32_t all[4] = {pl[2*j][0], pl[2*j][1], pl[2*j+1][0], pl[2*j+1][1]};
                #pragma unroll
                for (int nv = 0; nv < 5; nv++) {
                    uint32_t bvh[2], bvl[2];
                    LDM_X2(bvh[0], bvh[1], sb + AT_V(st)  + ((nv*8 + vrow) * VP + j*16 + vcsel) * 2);
                    LDM_X2(bvl[0], bvl[1], sb + AT_VL(st) + ((nv*8 + vrow) * VP + j*16 + vcsel) * 2);
                    MMA_BF16(o[nv], ahh, bvh);
                    MMA_BF16(o[nv], all, bvh);
                    MMA_BF16(o[nv], ahh, bvl);
                }
            }
        }
        __syncthreads();
    }

    // ---- epilogue ----
    const float l0 = __shfl_sync(0xffffffff, o[4][0], lane & 28);
    const float l1 = __shfl_sync(0xffffffff, o[4][2], lane & 28);
    const float inv0 = (l0 > 0.f) ? (1.f / l0) : 0.f;
    const float inv1 = (l1 > 0.f) ? (1.f / l1) : 0.f;
    const int e0 = qt * 128 + wid * 16 + (lane >> 2);
    #pragma unroll
    for (int nv = 0; nv < 4; nv++) {
        const int col = h * 32 + nv * 8 + (lane & 3) * 2;
        float v0 = o[nv][0] * inv0, v1 = o[nv][1] * inv0;
        float v2 = o[nv][2] * inv1, v3 = o[nv][3] * inv1;
        __nv_bfloat16 h0 = __float2bfloat16(v0), h1 = __float2bfloat16(v1);
        __nv_bfloat16 h2 = __float2bfloat16(v2), h3 = __float2bfloat16(v3);
        size_t o0 = ((size_t)(b * Ec + e0)) * Dc + col;
        size_t o1 = ((size_t)(b * Ec + e0 + 8)) * Dc + col;
        *(__nv_bfloat162*)(g_athi + o0) = __nv_bfloat162{h0, h1};
        *(__nv_bfloat162*)(g_athi + o1) = __nv_bfloat162{h2, h3};
        *(__nv_bfloat162*)(g_atlo + o0) = __nv_bfloat162{
            __float2bfloat16(v0 - __bfloat162float(h0)), __float2bfloat16(v1 - __bfloat162float(h1))};
        *(__nv_bfloat162*)(g_atlo + o1) = __nv_bfloat162{
            __float2bfloat16(v2 - __bfloat162float(h2)), __float2bfloat16(v3 - __bfloat162float(h3))};
    }
}

// ======================= LayerNorm ==========================================
__global__ __launch_bounds__(256)
void ln_kernel(const float* __restrict__ x, const float* __restrict__ g,
               const float* __restrict__ be, float* __restrict__ y,
               __nv_bfloat16* __restrict__ yhi, __nv_bfloat16* __restrict__ ylo)
{
    int row = blockIdx.x * 8 + (threadIdx.x >> 5);
    int lane = threadIdx.x & 31;
    const float* xr = x + (size_t)row * Dc;
    float v[8], sum = 0.f;
    #pragma unroll
    for (int i = 0; i < 8; i++) { v[i] = xr[lane + i * 32]; sum += v[i]; }
    #pragma unroll
    for (int o = 16; o; o >>= 1) sum += __shfl_xor_sync(0xffffffff, sum, o);
    float mu = sum * (1.f / Dc);
    float var = 0.f;
    #pragma unroll
    for (int i = 0; i < 8; i++) { float d = v[i] - mu; var += d * d; }
    #pragma unroll
    for (int o = 16; o; o >>= 1) var += __shfl_xor_sync(0xffffffff, var, o);
    float rstd = rsqrtf(var * (1.f / Dc) + 1e-5f);
    float* yr = y + (size_t)row * Dc;
    #pragma unroll
    for (int i = 0; i < 8; i++) {
        int c = lane + i * 32;
        float val = (v[i] - mu) * rstd * g[c] + be[c];
        yr[c] = val;
        if (yhi) {
            __nv_bfloat16 hh = __float2bfloat16(val);
            yhi[(size_t)row * Dc + c] = hh;
            ylo[(size_t)row * Dc + c] = __float2bfloat16(val - __bfloat162float(hh));
        }
    }
}

// ======================= launch =============================================
static void* sym(const void* s) { void* p = nullptr; cudaGetSymbolAddress(&p, s); return p; }

extern "C" void kernel_launch(void* const* d_in, const int* in_sizes, int n_in,
                              void* d_out, int out_size)
{
    const float* x    = (const float*)d_in[0];
    const int*   srel = (const int*)  d_in[1];
    const unsigned char* mraw = (const unsigned char*)d_in[2];
    const float* wq = (const float*)d_in[3];  const float* bq = (const float*)d_in[4];
    const float* wk = (const float*)d_in[5];  const float* bk = (const float*)d_in[6];
    const float* wv = (const float*)d_in[7];  const float* bv = (const float*)d_in[8];
    const float* wo = (const float*)d_in[9];  const float* bo = (const float*)d_in[10];
    const float* bias_emb = (const float*)d_in[11];
    const float* g1 = (const float*)d_in[12]; const float* be1 = (const float*)d_in[13];
    const float* w1 = (const float*)d_in[14]; const float* b1f = (const float*)d_in[15];
    const float* w2 = (const float*)d_in[16]; const float* b2f = (const float*)d_in[17];
    const float* g2 = (const float*)d_in[18]; const float* be2 = (const float*)d_in[19];
    float* out = (float*)d_out;

    float* res1 = (float*)sym(g_res1);
    float* h1   = (float*)sym(g_h1);
    float* res2 = (float*)sym(g_res2);
    __nv_bfloat16* xhi  = (__nv_bfloat16*)sym(g_xhi);
    __nv_bfloat16* xlo  = (__nv_bfloat16*)sym(g_xlo);
    __nv_bfloat16* qhi  = (__nv_bfloat16*)sym(g_qhi);  __nv_bfloat16* qlo  = (__nv_bfloat16*)sym(g_qlo);
    __nv_bfloat16* khi  = (__nv_bfloat16*)sym(g_khi);  __nv_bfloat16* klo  = (__nv_bfloat16*)sym(g_klo);
    __nv_bfloat16* vthi = (__nv_bfloat16*)sym(g_vthi); __nv_bfloat16* vtlo = (__nv_bfloat16*)sym(g_vtlo);
    __nv_bfloat16* athi = (__nv_bfloat16*)sym(g_athi); __nv_bfloat16* atlo = (__nv_bfloat16*)sym(g_atlo);
    __nv_bfloat16* h1hi = (__nv_bfloat16*)sym(g_h1hi); __nv_bfloat16* h1lo = (__nv_bfloat16*)sym(g_h1lo);
    __nv_bfloat16* f1hi = (__nv_bfloat16*)sym(g_f1hi); __nv_bfloat16* f1lo = (__nv_bfloat16*)sym(g_f1lo);
    __nv_bfloat16* wqthi = (__nv_bfloat16*)sym(g_wqthi); __nv_bfloat16* wqtlo = (__nv_bfloat16*)sym(g_wqtlo);
    __nv_bfloat16* wkthi = (__nv_bfloat16*)sym(g_wkthi); __nv_bfloat16* wktlo = (__nv_bfloat16*)sym(g_wktlo);
    __nv_bfloat16* wvthi = (__nv_bfloat16*)sym(g_wvthi); __nv_bfloat16* wvtlo = (__nv_bfloat16*)sym(g_wvtlo);
    __nv_bfloat16* wothi = (__nv_bfloat16*)sym(g_wothi); __nv_bfloat16* wotlo = (__nv_bfloat16*)sym(g_wotlo);
    __nv_bfloat16* w1thi = (__nv_bfloat16*)sym(g_w1thi); __nv_bfloat16* w1tlo = (__nv_bfloat16*)sym(g_w1tlo);
    __nv_bfloat16* w2thi = (__nv_bfloat16*)sym(g_w2thi); __nv_bfloat16* w2tlo = (__nv_bfloat16*)sym(g_w2tlo);

    cudaFuncSetAttribute(mma_gemm<1>, cudaFuncAttributeMaxDynamicSharedMemorySize, SMEM_G);
    cudaFuncSetAttribute(mma_gemm<2>, cudaFuncAttributeMaxDynamicSharedMemorySize, SMEM_G);
    cudaFuncSetAttribute(mma_gemm<4>, cudaFuncAttributeMaxDynamicSharedMemorySize, SMEM_G);
    cudaFuncSetAttribute(mma_gemm<6>, cudaFuncAttributeMaxDynamicSharedMemorySize, SMEM_G);
    cudaFuncSetAttribute(attn_mma, cudaFuncAttributeMaxDynamicSharedMemorySize, AT_SMEM);

    dim3 b32(32, 8);
    const float qscale = 0.17677669529663687f;  // 1/sqrt(32)

    // launch order arranged so ncu (-s 5) profiles mma_gemm<4> (Q projection)
    split_kernel<<<(Mrows*Dc + 255) / 256, 256>>>(x, xhi, xlo, Mrows*Dc);                 // 0
    wsplit_kernel<<<dim3(Dc/32, Dc/32), b32>>>(wq, Dc, Dc, wqthi, wqtlo);                 // 1
    detect_mask_kernel<<<1, 256>>>(mraw);                                                  // 2
    canon_mask_kernel<<<(Bc*Ec + 255) / 256, 256>>>(mraw);                                 // 3
    detect_bias_kernel<<<1, 64>>>(bias_emb);                                               // 4
    mma_gemm<4><<<dim3(2, 64), 256, SMEM_G>>>(Mrows, Dc, Dc, xhi, xlo, wqthi, wqtlo,
                                              bq, nullptr, nullptr, qhi, qlo, qscale);     // 5 <- profiled
    wsplit_kernel<<<dim3(Dc/32, Dc/32), b32>>>(wk, Dc, Dc, wkthi, wktlo);                 // 6
    mma_gemm<4><<<dim3(2, 64), 256, SMEM_G>>>(Mrows, Dc, Dc, xhi, xlo, wkthi, wktlo,
                                              bk, nullptr, nullptr, khi, klo, 1.f);        // 7
    wsplit_kernel<<<dim3(Dc/32, Dc/32), b32>>>(wv, Dc, Dc, wvthi, wvtlo);                 // 8
    mma_gemm<6><<<dim3(2, 64), 256, SMEM_G>>>(Mrows, Dc, Dc, xhi, xlo, wvthi, wvtlo,
                                              bv, nullptr, nullptr, vthi, vtlo, 1.f);      // 9
    attn_mma<<<dim3(Bc*Hc, Ec/128), 256, AT_SMEM>>>(srel, bias_emb);                       // 10
    wsplit_kernel<<<dim3(Dc/32, Dc/32), b32>>>(wo, Dc, Dc, wothi, wotlo);                 // 11
    mma_gemm<1><<<dim3(2, 64), 256, SMEM_G>>>(Mrows, Dc, Dc, athi, atlo, wothi, wotlo,
                                              bo, x, res1, nullptr, nullptr, 1.f);         // 12
    ln_kernel<<<Mrows/8, 256>>>(res1, g1, be1, h1, h1hi, h1lo);                            // 13
    wsplit_kernel<<<dim3(FF/32, Dc/32), b32>>>(w1, Dc, FF, w1thi, w1tlo);                 // 14
    mma_gemm<2><<<dim3(8, 64), 256, SMEM_G>>>(Mrows, FF, Dc, h1hi, h1lo, w1thi, w1tlo,
                                              b1f, nullptr, nullptr, f1hi, f1lo, 1.f);     // 15
    wsplit_kernel<<<dim3(Dc/32, FF/32), b32>>>(w2, FF, Dc, w2thi, w2tlo);                 // 16
    mma_gemm<1><<<dim3(2, 64), 256, SMEM_G>>>(Mrows, Dc, FF, f1hi, f1lo, w2thi, w2tlo,
                                              b2f, h1, res2, nullptr, nullptr, 1.f);       // 17
    ln_kernel<<<Mrows/8, 256>>>(res2, g2, be2, out, nullptr, nullptr);                     // 18
}

// round 6
// speedup vs baseline: 2.9261x; 1.1807x over previous
#include <cuda_runtime.h>
#include <cuda_bf16.h>
#include <math.h>
#include <stdint.h>

#define Bc 8
#define Ec 1024
#define Dc 256
#define Hc 8
#define HDc 32
#define NBc 6
#define Mrows (Bc*Ec)   // 8192
#define FF (4*Dc)       // 1024

// ======================= scratch (device globals) ===========================
__device__ float g_res1[Mrows*Dc];
__device__ float g_h1[Mrows*Dc];
__device__ float g_res2[Mrows*Dc];
__device__ int   g_mask[Bc*Ec];
__device__ int   g_bflag[1];
__device__ __nv_bfloat16 g_ones[Bc*Ec];

// split-bf16 activations
__device__ __nv_bfloat16 g_xhi[Mrows*Dc],  g_xlo[Mrows*Dc];
__device__ __nv_bfloat16 g_qhi[Mrows*Dc],  g_qlo[Mrows*Dc];   // [B,H,E,HD]
__device__ __nv_bfloat16 g_khi[Mrows*Dc],  g_klo[Mrows*Dc];   // [B,H,E,HD]
__device__ __nv_bfloat16 g_vthi[Mrows*Dc], g_vtlo[Mrows*Dc];  // [B,H,HD,E]
__device__ __nv_bfloat16 g_athi[Mrows*Dc], g_atlo[Mrows*Dc];  // [B,E,D]
__device__ __nv_bfloat16 g_h1hi[Mrows*Dc], g_h1lo[Mrows*Dc];
__device__ __nv_bfloat16 g_f1hi[Mrows*FF], g_f1lo[Mrows*FF];
// split-bf16 transposed weights ([N,K] layout)
__device__ __nv_bfloat16 g_wqthi[Dc*Dc], g_wqtlo[Dc*Dc];
__device__ __nv_bfloat16 g_wkthi[Dc*Dc], g_wktlo[Dc*Dc];
__device__ __nv_bfloat16 g_wvthi[Dc*Dc], g_wvtlo[Dc*Dc];
__device__ __nv_bfloat16 g_wothi[Dc*Dc], g_wotlo[Dc*Dc];
__device__ __nv_bfloat16 g_w1thi[FF*Dc], g_w1tlo[FF*Dc];
__device__ __nv_bfloat16 g_w2thi[Dc*FF], g_w2tlo[Dc*FF];

// ======================= helpers ============================================
__device__ __forceinline__ uint32_t smem_u32(const void* p) {
    uint32_t a;
    asm("{ .reg .u64 t; cvta.to.shared.u64 t, %1; cvt.u32.u64 %0, t; }" : "=r"(a) : "l"(p));
    return a;
}
__device__ __forceinline__ void cpa16(uint32_t d, const void* s) {
    asm volatile("cp.async.cg.shared.global [%0], [%1], 16;" :: "r"(d), "l"(s));
}
#define LDM_X4(r0,r1,r2,r3,addr) \
    asm volatile("ldmatrix.sync.aligned.m8n8.x4.shared.b16 {%0,%1,%2,%3}, [%4];" \
        : "=r"(r0),"=r"(r1),"=r"(r2),"=r"(r3) : "r"(addr))
#define LDM_X2(r0,r1,addr) \
    asm volatile("ldmatrix.sync.aligned.m8n8.x2.shared.b16 {%0,%1}, [%2];" \
        : "=r"(r0),"=r"(r1) : "r"(addr))
#define MMA_BF16(d,a,b) \
    asm volatile("mma.sync.aligned.m16n8k16.row.col.f32.bf16.bf16.f32 " \
        "{%0,%1,%2,%3}, {%4,%5,%6,%7}, {%8,%9}, {%0,%1,%2,%3};" \
        : "+f"((d)[0]),"+f"((d)[1]),"+f"((d)[2]),"+f"((d)[3]) \
        : "r"((a)[0]),"r"((a)[1]),"r"((a)[2]),"r"((a)[3]),"r"((b)[0]),"r"((b)[1]))

__device__ __forceinline__ float gelu_exact(float v) {
    return 0.5f * v * (1.0f + erff(v * 0.70710678118654752f));
}
__device__ __forceinline__ uint32_t pack_bf16(float a, float b) {
    __nv_bfloat162 t = __floats2bfloat162_rn(a, b);
    return *(uint32_t*)&t;
}
// SW64 swizzle on byte offsets (8 rows x 64B atom)
#define SWZ64(o) ((o) ^ (((o) >> 3) & 0x30))

// ======================= prep kernels =======================================
__global__ void mask_kernel(const unsigned char* __restrict__ raw) {
    __shared__ int found;
    const int tid = threadIdx.x;
    if (tid == 0) found = 0;
    __syncthreads();
    int loc = 0;
    for (int i = tid; i < Bc*Ec; i += 1024)
        if ((i & 3) && raw[i]) loc = 1;
    if (loc) atomicOr(&found, 1);
    __syncthreads();
    const int isInt = !found;
    for (int i = tid; i < Bc*Ec; i += 1024) {
        int m = isInt ? (((const int*)raw)[i] != 0) : (raw[i] != 0);
        g_mask[i] = m;
        g_ones[i] = __float2bfloat16(m ? 0.f : 1.f);
    }
}
__global__ void detect_bias_kernel(const float* __restrict__ be) {
    __shared__ int f;
    if (threadIdx.x == 0) f = 0;
    __syncthreads();
    if (threadIdx.x < NBc*Hc && be[threadIdx.x] != 0.f) atomicOr(&f, 1);
    __syncthreads();
    if (threadIdx.x == 0) g_bflag[0] = f;
}

// ======================= split conversions ==================================
__global__ void split_kernel(const float* __restrict__ x,
                             __nv_bfloat16* __restrict__ hi, __nv_bfloat16* __restrict__ lo, int n) {
    int i = blockIdx.x * 256 + threadIdx.x;
    if (i < n) {
        float v = x[i];
        __nv_bfloat16 h = __float2bfloat16(v);
        hi[i] = h;
        lo[i] = __float2bfloat16(v - __bfloat162float(h));
    }
}
// W [K,N] fp32 -> Wt [N,K] split bf16
__device__ __forceinline__ void wsplit_body(const float* W, int K, int N,
                                            __nv_bfloat16* Thi, __nv_bfloat16* Tlo,
                                            int bx, int by) {
    __shared__ float t[32][33];
    int n0 = bx * 32, k0 = by * 32;
    for (int i = threadIdx.y; i < 32; i += 8)
        t[i][threadIdx.x] = W[(size_t)(k0 + i) * N + n0 + threadIdx.x];
    __syncthreads();
    for (int i = threadIdx.y; i < 32; i += 8) {
        float v = t[threadIdx.x][i];
        size_t o = (size_t)(n0 + i) * K + k0 + threadIdx.x;
        __nv_bfloat16 h = __float2bfloat16(v);
        Thi[o] = h;
        Tlo[o] = __float2bfloat16(v - __bfloat162float(h));
    }
}
__global__ void wsplit_kernel(const float* __restrict__ W, int K, int N,
                              __nv_bfloat16* __restrict__ Thi, __nv_bfloat16* __restrict__ Tlo) {
    wsplit_body(W, K, N, Thi, Tlo, blockIdx.x, blockIdx.y);
}
// batched QKVO weight split (all D x D)
__global__ void wsplit4_kernel(const float* __restrict__ wq, const float* __restrict__ wk,
                               const float* __restrict__ wv, const float* __restrict__ wo) {
    const float* W;
    __nv_bfloat16 *Thi, *Tlo;
    switch (blockIdx.z) {
        case 0:  W = wq; Thi = g_wqthi; Tlo = g_wqtlo; break;
        case 1:  W = wk; Thi = g_wkthi; Tlo = g_wktlo; break;
        case 2:  W = wv; Thi = g_wvthi; Tlo = g_wvtlo; break;
        default: W = wo; Thi = g_wothi; Tlo = g_wotlo; break;
    }
    wsplit_body(W, Dc, Dc, Thi, Tlo, blockIdx.x, blockIdx.y);
}

// ======================= split-bf16 GEMM core ===============================
// smem: 2 stages x 4 tiles x (128 rows x 64B, SW64) = 64 KB
#define TILE_B 8192
#define STAGE_B 32768
#define SMEM_G 65536

__device__ __forceinline__ void load_stage_g(
    const __nv_bfloat16* const* src, int K, int kc,
    uint32_t sb, int stage, int tid)
{
    #pragma unroll
    for (int t = 0; t < 4; t++) {
        uint32_t dst = sb + stage * STAGE_B + t * TILE_B;
        #pragma unroll
        for (int i = 0; i < 2; i++) {
            int idx = tid + i * 256;
            int row = idx >> 2, seg = idx & 3;
            cpa16(dst + SWZ64(row * 64 + seg * 16),
                  src[t] + (size_t)row * K + kc + seg * 8);
        }
    }
}

// mainloop: fills acc[4][4][4] for a 128x128 tile, A/B split-bf16 3-term
__device__ __forceinline__ void gemm_main(
    float acc[4][4][4],
    const __nv_bfloat16* Am_hi, const __nv_bfloat16* Am_lo,
    const __nv_bfloat16* Bn_hi, const __nv_bfloat16* Bn_lo,
    int K, uint32_t sb, int tid)
{
    const int lane = tid & 31, wid = tid >> 5;
    const int wm = wid & 1, wn = wid >> 1;
    const __nv_bfloat16* src[4] = { Am_hi, Am_lo, Bn_hi, Bn_lo };

    #pragma unroll
    for (int a = 0; a < 4; a++)
        #pragma unroll
        for (int b = 0; b < 4; b++)
            #pragma unroll
            for (int c = 0; c < 4; c++) acc[a][b][c] = 0.f;

    const int NC = K / 32;
    load_stage_g(src, K, 0, sb, 0, tid);
    asm volatile("cp.async.commit_group;");

    for (int c = 0; c < NC; c++) {
        const int stage = c & 1;
        if (c + 1 < NC) {
            load_stage_g(src, K, (c + 1) * 32, sb, stage ^ 1, tid);
            asm volatile("cp.async.commit_group;");
            asm volatile("cp.async.wait_group 1;");
        } else {
            asm volatile("cp.async.wait_group 0;");
        }
        __syncthreads();

        const uint32_t As_hi = sb + stage * STAGE_B;
        const uint32_t As_lo = As_hi + TILE_B;
        const uint32_t Bs_hi = As_hi + 2 * TILE_B;
        const uint32_t Bs_lo = As_hi + 3 * TILE_B;

        #pragma unroll
        for (int k16 = 0; k16 < 2; k16++) {
            uint32_t ah[4][4], bh[4][2], bl[4][2];
            const int arow = wm * 64 + (lane & 15);
            const int acolb = k16 * 32 + (lane >> 4) * 16;
            #pragma unroll
            for (int mt = 0; mt < 4; mt++)
                LDM_X4(ah[mt][0], ah[mt][1], ah[mt][2], ah[mt][3],
                       As_hi + SWZ64((arow + mt * 16) * 64 + acolb));
            const int brow = wn * 32 + (lane & 7);
            const int bcolb = k16 * 32 + ((lane >> 3) & 1) * 16;
            #pragma unroll
            for (int nt = 0; nt < 4; nt++) {
                LDM_X2(bh[nt][0], bh[nt][1], Bs_hi + SWZ64((brow + nt * 8) * 64 + bcolb));
                LDM_X2(bl[nt][0], bl[nt][1], Bs_lo + SWZ64((brow + nt * 8) * 64 + bcolb));
            }
            #pragma unroll
            for (int mt = 0; mt < 4; mt++)
                #pragma unroll
                for (int nt = 0; nt < 4; nt++) {
                    MMA_BF16(acc[mt][nt], ah[mt], bh[nt]);
                    MMA_BF16(acc[mt][nt], ah[mt], bl[nt]);
                }
            #pragma unroll
            for (int mt = 0; mt < 4; mt++)
                LDM_X4(ah[mt][0], ah[mt][1], ah[mt][2], ah[mt][3],
                       As_lo + SWZ64((arow + mt * 16) * 64 + acolb));
            #pragma unroll
            for (int mt = 0; mt < 4; mt++)
                #pragma unroll
                for (int nt = 0; nt < 4; nt++)
                    MMA_BF16(acc[mt][nt], ah[mt], bh[nt]);
        }
        __syncthreads();
    }
}

// ---- generic GEMM (MODE 1: +bias+res fp32; MODE 2: split of gelu(+bias)) ----
template<int MODE>
__global__ __launch_bounds__(256, 2)
void mma_gemm(int M, int N, int K,
              const __nv_bfloat16* __restrict__ Ahi, const __nv_bfloat16* __restrict__ Alo,
              const __nv_bfloat16* __restrict__ Bhi, const __nv_bfloat16* __restrict__ Blo,
              const float* __restrict__ bias, const float* __restrict__ res,
              float* __restrict__ C,
              __nv_bfloat16* __restrict__ Chi, __nv_bfloat16* __restrict__ Clo)
{
    extern __shared__ char smg[];
    const uint32_t sb = smem_u32(smg);
    const int tid = threadIdx.x, lane = tid & 31, wid = tid >> 5;
    const int wm = wid & 1, wn = wid >> 1;
    const int n0 = blockIdx.x * 128, m0 = blockIdx.y * 128;

    float acc[4][4][4];
    gemm_main(acc, Ahi + (size_t)m0 * K, Alo + (size_t)m0 * K,
              Bhi + (size_t)n0 * K, Blo + (size_t)n0 * K, K, sb, tid);

    #pragma unroll
    for (int mt = 0; mt < 4; mt++) {
        const int r0 = m0 + wm * 64 + mt * 16 + (lane >> 2);
        #pragma unroll
        for (int nt = 0; nt < 4; nt++) {
            const int gc = n0 + wn * 32 + nt * 8 + (lane & 3) * 2;
            const float b0 = bias[gc], b1 = bias[gc + 1];
            #pragma unroll
            for (int half = 0; half < 2; half++) {
                const int row = r0 + half * 8;
                float v0 = acc[mt][nt][half * 2 + 0] + b0;
                float v1 = acc[mt][nt][half * 2 + 1] + b1;
                if (MODE == 1) {
                    const float2 rr = *(const float2*)(res + (size_t)row * N + gc);
                    *(float2*)(C + (size_t)row * N + gc) = make_float2(v0 + rr.x, v1 + rr.y);
                } else {
                    float gv0 = gelu_exact(v0), gv1 = gelu_exact(v1);
                    __nv_bfloat16 h0 = __float2bfloat16(gv0), h1 = __float2bfloat16(gv1);
                    size_t o = (size_t)row * N + gc;
                    *(__nv_bfloat162*)(Chi + o) = __nv_bfloat162{h0, h1};
                    *(__nv_bfloat162*)(Clo + o) = __nv_bfloat162{
                        __float2bfloat16(gv0 - __bfloat162float(h0)),
                        __float2bfloat16(gv1 - __bfloat162float(h1))};
                }
            }
        }
    }
}

// ---- fused QKV GEMM: grid (6, 64); bx>>1 selects Q/K/V --------------------
__global__ __launch_bounds__(256, 2)
void qkv_gemm(const __nv_bfloat16* __restrict__ Ahi, const __nv_bfloat16* __restrict__ Alo,
              const float* __restrict__ bq, const float* __restrict__ bk,
              const float* __restrict__ bv)
{
    extern __shared__ char smg[];
    const uint32_t sb = smem_u32(smg);
    const int tid = threadIdx.x, lane = tid & 31, wid = tid >> 5;
    const int wm = wid & 1, wn = wid >> 1;
    const int which = blockIdx.x >> 1;          // 0=Q, 1=K, 2=V
    const int n0 = (blockIdx.x & 1) * 128;
    const int m0 = blockIdx.y * 128;

    const __nv_bfloat16 *Bhi, *Blo;
    const float* bias;
    if (which == 0)      { Bhi = g_wqthi; Blo = g_wqtlo; bias = bq; }
    else if (which == 1) { Bhi = g_wkthi; Blo = g_wktlo; bias = bk; }
    else                 { Bhi = g_wvthi; Blo = g_wvtlo; bias = bv; }

    float acc[4][4][4];
    gemm_main(acc, Ahi + (size_t)m0 * Dc, Alo + (size_t)m0 * Dc,
              Bhi + (size_t)n0 * Dc, Blo + (size_t)n0 * Dc, Dc, sb, tid);

    const float scl = (which == 0) ? 0.17677669529663687f : 1.f;
    __nv_bfloat16* Chi = (which == 0) ? g_qhi : (which == 1) ? g_khi : g_vthi;
    __nv_bfloat16* Clo = (which == 0) ? g_qlo : (which == 1) ? g_klo : g_vtlo;

    #pragma unroll
    for (int mt = 0; mt < 4; mt++) {
        const int r0 = m0 + wm * 64 + mt * 16 + (lane >> 2);
        #pragma unroll
        for (int nt = 0; nt < 4; nt++) {
            const int gc = n0 + wn * 32 + nt * 8 + (lane & 3) * 2;
            const float b0 = bias[gc], b1 = bias[gc + 1];
            #pragma unroll
            for (int half = 0; half < 2; half++) {
                const int row = r0 + half * 8;
                const int bb = row >> 10, e = row & 1023;
                const int h2 = gc >> 5, hd = gc & 31;
                float v0 = (acc[mt][nt][half * 2 + 0] + b0) * scl;
                float v1 = (acc[mt][nt][half * 2 + 1] + b1) * scl;
                if (which < 2) {  // Q/K -> [B,H,E,HD]
                    __nv_bfloat16 h0 = __float2bfloat16(v0), h1 = __float2bfloat16(v1);
                    size_t o = (((size_t)(bb * Hc + h2) * Ec + e)) * HDc + hd;
                    *(__nv_bfloat162*)(Chi + o) = __nv_bfloat162{h0, h1};
                    *(__nv_bfloat162*)(Clo + o) = __nv_bfloat162{
                        __float2bfloat16(v0 - __bfloat162float(h0)),
                        __float2bfloat16(v1 - __bfloat162float(h1))};
                } else {          // V^T -> [B,H,HD,E], mask-zeroed
                    if (g_mask[bb * Ec + e]) { v0 = 0.f; v1 = 0.f; }
                    size_t o = (((size_t)(bb * Hc + h2) * HDc + hd)) * Ec + e;
                    __nv_bfloat16 h0 = __float2bfloat16(v0), h1 = __float2bfloat16(v1);
                    Chi[o] = h0; Chi[o + Ec] = h1;
                    Clo[o]      = __float2bfloat16(v0 - __bfloat162float(h0));
                    Clo[o + Ec] = __float2bfloat16(v1 - __bfloat162float(h1));
                }
            }
        }
    }
}

// ======================= MMA FlashAttention (unchanged from R5) =============
#define PAT 40
#define VP 136
#define VTILE_B (40*272)
#define AT_Q   0
#define AT_QL  10240
#define AT_K(s)  (20480 + (s)*10240)
#define AT_KL(s) (40960 + (s)*10240)
#define AT_V(s)  (61440 + (s)*VTILE_B)
#define AT_VL(s) (61440 + 2*VTILE_B + (s)*VTILE_B)
#define AT_BSH   (61440 + 4*VTILE_B)
#define AT_SMEM  (AT_BSH + 256)

__global__ __launch_bounds__(256)
void attn_mma(const int* __restrict__ srel, const float* __restrict__ bias_emb)
{
    extern __shared__ char sm[];
    const uint32_t sb = smem_u32(sm);
    const int tid = threadIdx.x, lane = tid & 31, wid = tid >> 5;
    const int bh = blockIdx.x, qt = blockIdx.y;
    const int b = bh >> 3, h = bh & 7;
    const int bias_nz = g_bflag[0];

    if (tid < NBc*Hc) ((float*)(sm + AT_BSH))[tid] = bias_emb[tid];

    for (int i = tid; i < 4 * 544; i += 256) {
        int buf = i / 544, off = i % 544;
        uint32_t base = (buf & 1) ? AT_VL(buf >> 1) : AT_V(buf >> 1);
        *(uint32_t*)(sm + base + 32 * 272 + off * 4) = 0;
    }

    const __nv_bfloat16* qhi = g_qhi + ((size_t)bh * Ec + qt * 128) * HDc;
    const __nv_bfloat16* qlo = g_qlo + ((size_t)bh * Ec + qt * 128) * HDc;

    #pragma unroll
    for (int i = 0; i < 2; i++) {
        int idx = tid + i * 256, r = idx >> 2, sg = idx & 3;
        cpa16(sb + AT_Q  + r * 80 + sg * 16, qhi + r * HDc + sg * 8);
        cpa16(sb + AT_QL + r * 80 + sg * 16, qlo + r * HDc + sg * 8);
    }
    {
        const __nv_bfloat16* khi = g_khi + (size_t)bh * Ec * HDc;
        const __nv_bfloat16* klo = g_klo + (size_t)bh * Ec * HDc;
        const __nv_bfloat16* vhi = g_vthi + (size_t)bh * HDc * Ec;
        const __nv_bfloat16* vlo = g_vtlo + (size_t)bh * HDc * Ec;
        #pragma unroll
        for (int i = 0; i < 2; i++) {
            int idx = tid + i * 256, r = idx >> 2, sg = idx & 3;
            cpa16(sb + AT_K(0)  + r * 80 + sg * 16, khi + r * HDc + sg * 8);
            cpa16(sb + AT_KL(0) + r * 80 + sg * 16, klo + r * HDc + sg * 8);
        }
        #pragma unroll
        for (int i = 0; i < 2; i++) {
            int idx = tid + i * 256, r = idx >> 4, sg = idx & 15;
            cpa16(sb + AT_V(0)  + r * 272 + sg * 16, vhi + (size_t)r * Ec + sg * 8);
            cpa16(sb + AT_VL(0) + r * 272 + sg * 16, vlo + (size_t)r * Ec + sg * 8);
        }
        if (tid < 16) cpa16(sb + AT_V(0) + 32 * 272 + tid * 16, g_ones + b * Ec + tid * 8);
    }
    asm volatile("cp.async.commit_group;");

    float m0 = -INFINITY, m1 = -INFINITY;
    float o[5][4];
    #pragma unroll
    for (int nv = 0; nv < 5; nv++)
        #pragma unroll
        for (int j = 0; j < 4; j++) o[nv][j] = 0.f;
    uint32_t qfh[2][4], qfl[2][4];

    for (int c = 0; c < 8; c++) {
        const int st = c & 1;
        const int kt = c * 128;
        if (c < 7) {
            const int ktn = kt + 128;
            const __nv_bfloat16* khi = g_khi + ((size_t)bh * Ec + ktn) * HDc;
            const __nv_bfloat16* klo = g_klo + ((size_t)bh * Ec + ktn) * HDc;
            const __nv_bfloat16* vhi = g_vthi + (size_t)bh * HDc * Ec + ktn;
            const __nv_bfloat16* vlo = g_vtlo + (size_t)bh * HDc * Ec + ktn;
            #pragma unroll
            for (int i = 0; i < 2; i++) {
                int idx = tid + i * 256, r = idx >> 2, sg = idx & 3;
                cpa16(sb + AT_K(st ^ 1)  + r * 80 + sg * 16, khi + r * HDc + sg * 8);
                cpa16(sb + AT_KL(st ^ 1) + r * 80 + sg * 16, klo + r * HDc + sg * 8);
            }
            #pragma unroll
            for (int i = 0; i < 2; i++) {
                int idx = tid + i * 256, r = idx >> 4, sg = idx & 15;
                cpa16(sb + AT_V(st ^ 1)  + r * 272 + sg * 16, vhi + (size_t)r * Ec + sg * 8);
                cpa16(sb + AT_VL(st ^ 1) + r * 272 + sg * 16, vlo + (size_t)r * Ec + sg * 8);
            }
            if (tid < 16) cpa16(sb + AT_V(st ^ 1) + 32 * 272 + tid * 16, g_ones + b * Ec + ktn + tid * 8);
            asm volatile("cp.async.commit_group;");
            asm volatile("cp.async.wait_group 1;");
        } else {
            asm volatile("cp.async.wait_group 0;");
        }
        __syncthreads();

        if (c == 0) {
            const int arow = wid * 16 + (lane & 15);
            const int acsel = (lane >> 4) * 8;
            #pragma unroll
            for (int k16 = 0; k16 < 2; k16++) {
                LDM_X4(qfh[k16][0], qfh[k16][1], qfh[k16][2], qfh[k16][3],
                       sb + AT_Q  + (arow * PAT + k16 * 16 + acsel) * 2);
                LDM_X4(qfl[k16][0], qfl[k16][1], qfl[k16][2], qfl[k16][3],
                       sb + AT_QL + (arow * PAT + k16 * 16 + acsel) * 2);
            }
        }

        float s[16][4];
        #pragma unroll
        for (int f = 0; f < 16; f++)
            #pragma unroll
            for (int j = 0; j < 4; j++) s[f][j] = 0.f;

        {
            const int krow = (lane & 15);
            const int kcsel = (lane >> 4) * 8;
            #pragma unroll
            for (int nt16 = 0; nt16 < 8; nt16++) {
                #pragma unroll
                for (int k16 = 0; k16 < 2; k16++) {
                    uint32_t h0,h1,h2,h3, l0,l1,l2,l3;
                    LDM_X4(h0,h1,h2,h3, sb + AT_K(st)  + ((nt16*16 + krow) * PAT + k16*16 + kcsel) * 2);
                    LDM_X4(l0,l1,l2,l3, sb + AT_KL(st) + ((nt16*16 + krow) * PAT + k16*16 + kcsel) * 2);
                    uint32_t bh0[2] = {h0, h2}, bh1[2] = {h1, h3};
                    uint32_t bl0[2] = {l0, l2}, bl1[2] = {l1, l3};
                    MMA_BF16(s[2*nt16],   qfh[k16], bh0);
                    MMA_BF16(s[2*nt16],   qfh[k16], bl0);
                    MMA_BF16(s[2*nt16],   qfl[k16], bh0);
                    MMA_BF16(s[2*nt16+1], qfh[k16], bh1);
                    MMA_BF16(s[2*nt16+1], qfh[k16], bl1);
                    MMA_BF16(s[2*nt16+1], qfl[k16], bh1);
                }
            }
        }

        if (bias_nz) {
            const float* bsh = (const float*)(sm + AT_BSH);
            const int q0 = qt * 128 + wid * 16 + (lane >> 2);
            #pragma unroll
            for (int f = 0; f < 16; f++) {
                const int key = kt + f * 8 + (lane & 3) * 2;
                const int* r0 = srel + ((size_t)b * Ec + q0) * Ec + key;
                const int* r1 = srel + ((size_t)b * Ec + q0 + 8) * Ec + key;
                s[f][0] += bsh[__ldg(r0)     * Hc + h];
                s[f][1] += bsh[__ldg(r0 + 1) * Hc + h];
                s[f][2] += bsh[__ldg(r1)     * Hc + h];
                s[f][3] += bsh[__ldg(r1 + 1) * Hc + h];
            }
        }

        float t0 = -INFINITY, t1 = -INFINITY;
        #pragma unroll
        for (int f = 0; f < 16; f++) {
            t0 = fmaxf(t0, fmaxf(s[f][0], s[f][1]));
            t1 = fmaxf(t1, fmaxf(s[f][2], s[f][3]));
        }
        t0 = fmaxf(t0, __shfl_xor_sync(0xffffffff, t0, 1));
        t0 = fmaxf(t0, __shfl_xor_sync(0xffffffff, t0, 2));
        t1 = fmaxf(t1, __shfl_xor_sync(0xffffffff, t1, 1));
        t1 = fmaxf(t1, __shfl_xor_sync(0xffffffff, t1, 2));
        const float mn0 = fmaxf(m0, t0), mn1 = fmaxf(m1, t1);
        const float cor0 = __expf(m0 - mn0), cor1 = __expf(m1 - mn1);
        m0 = mn0; m1 = mn1;
        #pragma unroll
        for (int nv = 0; nv < 5; nv++) {
            o[nv][0] *= cor0; o[nv][1] *= cor0;
            o[nv][2] *= cor1; o[nv][3] *= cor1;
        }
        uint32_t ph[16][2], pl[16][2];
        #pragma unroll
        for (int f = 0; f < 16; f++) {
            float p0 = __expf(s[f][0] - m0), p1 = __expf(s[f][1] - m0);
            float p2 = __expf(s[f][2] - m1), p3 = __expf(s[f][3] - m1);
            ph[f][0] = pack_bf16(p0, p1);
            ph[f][1] = pack_bf16(p2, p3);
            __nv_bfloat162 h01 = *(__nv_bfloat162*)&ph[f][0];
            __nv_bfloat162 h23 = *(__nv_bfloat162*)&ph[f][1];
            pl[f][0] = pack_bf16(p0 - __bfloat162float(h01.x), p1 - __bfloat162float(h01.y));
            pl[f][1] = pack_bf16(p2 - __bfloat162float(h23.x), p3 - __bfloat162float(h23.y));
        }

        {
            const int vrow = (lane & 7);
            const int vcsel = ((lane >> 3) & 1) * 8;
            #pragma unroll
            for (int j = 0; j < 8; j++) {
                uint32_t ahh[4] = {ph[2*j][0], ph[2*j][1], ph[2*j+1][0], ph[2*j+1][1]};
                uint32_t all[4] = {pl[2*j][0], pl[2*j][1], pl[2*j+1][0], pl[2*j+1][1]};
                #pragma unroll
                for (int nv = 0; nv < 5; nv++) {
                    uint32_t bvh[2], bvl[2];
                    LDM_X2(bvh[0], bvh[1], sb + AT_V(st)  + ((nv*8 + vrow) * VP + j*16 + vcsel) * 2);
                    LDM_X2(bvl[0], bvl[1], sb + AT_VL(st) + ((nv*8 + vrow) * VP + j*16 + vcsel) * 2);
                    MMA_BF16(o[nv], ahh, bvh);
                    MMA_BF16(o[nv], all, bvh);
                    MMA_BF16(o[nv], ahh, bvl);
                }
            }
        }
        __syncthreads();
    }

    const float l0 = __shfl_sync(0xffffffff, o[4][0], lane & 28);
    const float l1 = __shfl_sync(0xffffffff, o[4][2], lane & 28);
    const float inv0 = (l0 > 0.f) ? (1.f / l0) : 0.f;
    const float inv1 = (l1 > 0.f) ? (1.f / l1) : 0.f;
    const int e0 = qt * 128 + wid * 16 + (lane >> 2);
    #pragma unroll
    for (int nv = 0; nv < 4; nv++) {
        const int col = h * 32 + nv * 8 + (lane & 3) * 2;
        float v0 = o[nv][0] * inv0, v1 = o[nv][1] * inv0;
        float v2 = o[nv][2] * inv1, v3 = o[nv][3] * inv1;
        __nv_bfloat16 h0 = __float2bfloat16(v0), h1 = __float2bfloat16(v1);
        __nv_bfloat16 h2 = __float2bfloat16(v2), h3 = __float2bfloat16(v3);
        size_t o0 = ((size_t)(b * Ec + e0)) * Dc + col;
        size_t o1 = ((size_t)(b * Ec + e0 + 8)) * Dc + col;
        *(__nv_bfloat162*)(g_athi + o0) = __nv_bfloat162{h0, h1};
        *(__nv_bfloat162*)(g_athi + o1) = __nv_bfloat162{h2, h3};
        *(__nv_bfloat162*)(g_atlo + o0) = __nv_bfloat162{
            __float2bfloat16(v0 - __bfloat162float(h0)), __float2bfloat16(v1 - __bfloat162float(h1))};
        *(__nv_bfloat162*)(g_atlo + o1) = __nv_bfloat162{
            __float2bfloat16(v2 - __bfloat162float(h2)), __float2bfloat16(v3 - __bfloat162float(h3))};
    }
}

// ======================= LayerNorm ==========================================
__global__ __launch_bounds__(256)
void ln_kernel(const float* __restrict__ x, const float* __restrict__ g,
               const float* __restrict__ be, float* __restrict__ y,
               __nv_bfloat16* __restrict__ yhi, __nv_bfloat16* __restrict__ ylo)
{
    int row = blockIdx.x * 8 + (threadIdx.x >> 5);
    int lane = threadIdx.x & 31;
    const float* xr = x + (size_t)row * Dc;
    float v[8], sum = 0.f;
    #pragma unroll
    for (int i = 0; i < 8; i++) { v[i] = xr[lane + i * 32]; sum += v[i]; }
    #pragma unroll
    for (int o = 16; o; o >>= 1) sum += __shfl_xor_sync(0xffffffff, sum, o);
    float mu = sum * (1.f / Dc);
    float var = 0.f;
    #pragma unroll
    for (int i = 0; i < 8; i++) { float d = v[i] - mu; var += d * d; }
    #pragma unroll
    for (int o = 16; o; o >>= 1) var += __shfl_xor_sync(0xffffffff, var, o);
    float rstd = rsqrtf(var * (1.f / Dc) + 1e-5f);
    float* yr = y + (size_t)row * Dc;
    #pragma unroll
    for (int i = 0; i < 8; i++) {
        int c = lane + i * 32;
        float val = (v[i] - mu) * rstd * g[c] + be[c];
        yr[c] = val;
        if (yhi) {
            __nv_bfloat16 hh = __float2bfloat16(val);
            yhi[(size_t)row * Dc + c] = hh;
            ylo[(size_t)row * Dc + c] = __float2bfloat16(val - __bfloat162float(hh));
        }
    }
}

// ======================= launch =============================================
static void* sym(const void* s) { void* p = nullptr; cudaGetSymbolAddress(&p, s); return p; }

extern "C" void kernel_launch(void* const* d_in, const int* in_sizes, int n_in,
                              void* d_out, int out_size)
{
    const float* x    = (const float*)d_in[0];
    const int*   srel = (const int*)  d_in[1];
    const unsigned char* mraw = (const unsigned char*)d_in[2];
    const float* wq = (const float*)d_in[3];  const float* bq = (const float*)d_in[4];
    const float* wk = (const float*)d_in[5];  const float* bk = (const float*)d_in[6];
    const float* wv = (const float*)d_in[7];  const float* bv = (const float*)d_in[8];
    const float* wo = (const float*)d_in[9];  const float* bo = (const float*)d_in[10];
    const float* bias_emb = (const float*)d_in[11];
    const float* g1 = (const float*)d_in[12]; const float* be1 = (const float*)d_in[13];
    const float* w1 = (const float*)d_in[14]; const float* b1f = (const float*)d_in[15];
    const float* w2 = (const float*)d_in[16]; const float* b2f = (const float*)d_in[17];
    const float* g2 = (const float*)d_in[18]; const float* be2 = (const float*)d_in[19];
    float* out = (float*)d_out;

    float* res1 = (float*)sym(g_res1);
    float* h1   = (float*)sym(g_h1);
    float* res2 = (float*)sym(g_res2);
    __nv_bfloat16* xhi  = (__nv_bfloat16*)sym(g_xhi);
    __nv_bfloat16* xlo  = (__nv_bfloat16*)sym(g_xlo);
    __nv_bfloat16* athi = (__nv_bfloat16*)sym(g_athi); __nv_bfloat16* atlo = (__nv_bfloat16*)sym(g_atlo);
    __nv_bfloat16* h1hi = (__nv_bfloat16*)sym(g_h1hi); __nv_bfloat16* h1lo = (__nv_bfloat16*)sym(g_h1lo);
    __nv_bfloat16* f1hi = (__nv_bfloat16*)sym(g_f1hi); __nv_bfloat16* f1lo = (__nv_bfloat16*)sym(g_f1lo);
    __nv_bfloat16* wothi = (__nv_bfloat16*)sym(g_wothi); __nv_bfloat16* wotlo = (__nv_bfloat16*)sym(g_wotlo);
    __nv_bfloat16* w1thi = (__nv_bfloat16*)sym(g_w1thi); __nv_bfloat16* w1tlo = (__nv_bfloat16*)sym(g_w1tlo);
    __nv_bfloat16* w2thi = (__nv_bfloat16*)sym(g_w2thi); __nv_bfloat16* w2tlo = (__nv_bfloat16*)sym(g_w2tlo);

    cudaFuncSetAttribute(qkv_gemm,    cudaFuncAttributeMaxDynamicSharedMemorySize, SMEM_G);
    cudaFuncSetAttribute(mma_gemm<1>, cudaFuncAttributeMaxDynamicSharedMemorySize, SMEM_G);
    cudaFuncSetAttribute(mma_gemm<2>, cudaFuncAttributeMaxDynamicSharedMemorySize, SMEM_G);
    cudaFuncSetAttribute(attn_mma, cudaFuncAttributeMaxDynamicSharedMemorySize, AT_SMEM);

    dim3 b32(32, 8);

    // launch order: profiled slot is stream index 3 -> qkv_gemm
    split_kernel<<<(Mrows*Dc + 255) / 256, 256>>>(x, xhi, xlo, Mrows*Dc);                  // 0
    wsplit4_kernel<<<dim3(8, 8, 4), b32>>>(wq, wk, wv, wo);                                // 1
    mask_kernel<<<1, 1024>>>(mraw);                                                         // 2
    qkv_gemm<<<dim3(6, 64), 256, SMEM_G>>>(xhi, xlo, bq, bk, bv);                          // 3 <- profiled
    detect_bias_kernel<<<1, 64>>>(bias_emb);                                                // 4
    attn_mma<<<dim3(Bc*Hc, Ec/128), 256, AT_SMEM>>>(srel, bias_emb);                        // 5
    mma_gemm<1><<<dim3(2, 64), 256, SMEM_G>>>(Mrows, Dc, Dc, athi, atlo, wothi, wotlo,
                                              bo, x, res1, nullptr, nullptr);               // 6
    ln_kernel<<<Mrows/8, 256>>>(res1, g1, be1, h1, h1hi, h1lo);                             // 7
    wsplit_kernel<<<dim3(FF/32, Dc/32), b32>>>(w1, Dc, FF, w1thi, w1tlo);                  // 8
    mma_gemm<2><<<dim3(8, 64), 256, SMEM_G>>>(Mrows, FF, Dc, h1hi, h1lo, w1thi, w1tlo,
                                              b1f, nullptr, nullptr, f1hi, f1lo);           // 9
    wsplit_kernel<<<dim3(Dc/32, FF/32), b32>>>(w2, FF, Dc, w2thi, w2tlo);                  // 10
    mma_gemm<1><<<dim3(2, 64), 256, SMEM_G>>>(Mrows, Dc, FF, f1hi, f1lo, w2thi, w2tlo,
                                              b2f, h1, res2, nullptr, nullptr);             // 11
    ln_kernel<<<Mrows/8, 256>>>(res2, g2, be2, out, nullptr, nullptr);                      // 12
}